// round 5
// baseline (speedup 1.0000x reference)
#include <cuda_runtime.h>
#include <cstdint>

#define BATCH 16
#define NPTS  1024
#define FDIM  16
#define EDIM  12
#define HEADS 4
#define BB    32            // 2*BATCH (x-slab then y-slab)

typedef unsigned long long u64;

// ---------------- scratch (device globals; no allocation allowed) ----------
__device__ float g_x3  [BATCH*NPTS*3];
__device__ float g_yt3 [BATCH*3];
__device__ float g_q_s [BB*HEADS*NPTS*4];       // pre-scaled q (stride 4)
__device__ float g_kv_s[BB*HEADS*NPTS*12];      // duplicated: k0k0 k1k1 k2k2 v0v0 v1v1 v2v2
__device__ float g_q_c [BATCH*HEADS*NPTS*4];
__device__ float g_kv_c[BATCH*HEADS*NPTS*12];
__device__ float4 g_po_s[2*BB*HEADS*NPTS];      // split-KV partials: o0,o1,o2,l
__device__ float4 g_po_c[2*BATCH*HEADS*NPTS];
__device__ float g_statp[BATCH*4*16];           // 4 partial stat sets per batch
__device__ float g_Rt  [BATCH*12];              // R[9], t[3]

__device__ __forceinline__ float ex2f(float x) {
    float y; asm("ex2.approx.ftz.f32 %0, %1;" : "=f"(y) : "f"(x)); return y;
}
__device__ __forceinline__ u64 ffma2(u64 a, u64 b, u64 c) {
    u64 d; asm("fma.rn.f32x2 %0, %1, %2, %3;" : "=l"(d) : "l"(a), "l"(b), "l"(c)); return d;
}
__device__ __forceinline__ u64 fmul2(u64 a, u64 b) {
    u64 d; asm("mul.rn.f32x2 %0, %1, %2;" : "=l"(d) : "l"(a), "l"(b)); return d;
}
__device__ __forceinline__ u64 fadd2(u64 a, u64 b) {
    u64 d; asm("add.rn.f32x2 %0, %1, %2;" : "=l"(d) : "l"(a), "l"(b)); return d;
}
__device__ __forceinline__ u64 pack2(float lo, float hi) {
    u64 d; asm("mov.b64 %0, {%1, %2};" : "=l"(d) : "f"(lo), "f"(hi)); return d;
}
__device__ __forceinline__ void unpack2(u64 v, float& lo, float& hi) {
    asm("mov.b64 {%0, %1}, %2;" : "=f"(lo), "=f"(hi) : "l"(v));
}

// log2(e)/sqrt(3): fold softmax scale + base-2 conversion into Q
#define QSCALE ((float)(1.4426950408889634 / 1.7320508075688772))

// ============================================================================
// Kernel A: per (slab,batch,quarter): column means (redundant per quarter),
// center, input proj, self-QKV proj.  grid = 128 blocks, 256 threads.
// ============================================================================
__global__ __launch_bounds__(256) void prep_qkv_self(
    const float* __restrict__ x_orig, const float* __restrict__ y_orig,
    const float* __restrict__ W_in,   const float* __restrict__ b_in,
    const float* __restrict__ Wqkv_s, const float* __restrict__ bqkv_s)
{
    __shared__ float sW[EDIM*FDIM];
    __shared__ float sb[EDIM];
    __shared__ float sWq[36*EDIM];
    __shared__ float sbq[36];
    __shared__ float sred[256];
    __shared__ float smean[FDIM];

    const int tid  = threadIdx.x;
    const int s    = blockIdx.x >> 2;   // 0..31
    const int quar = blockIdx.x & 3;
    const int slab = s >> 4;            // 0 = x, 1 = y
    const int b    = s & 15;
    const float* in = (slab ? y_orig : x_orig) + (size_t)b * NPTS * FDIM;

    for (int i = tid; i < EDIM*FDIM; i += 256) sW[i]  = W_in[i];
    if (tid < EDIM) sb[tid] = b_in[tid];
    for (int i = tid; i < 36*EDIM;   i += 256) sWq[i] = Wqkv_s[i];
    if (tid < 36)   sbq[tid] = bqkv_s[tid];

    // column sums: thread (seg, f) sums 64 rows
    const int f = tid & 15, seg = tid >> 4;
    float acc = 0.f;
    for (int n = seg*64; n < seg*64 + 64; n++) acc += in[(size_t)n*FDIM + f];
    sred[tid] = acc;
    __syncthreads();
    if (tid < FDIM) {
        float m = 0.f;
        #pragma unroll
        for (int g = 0; g < 16; g++) m += sred[g*16 + tid];
        m *= (1.0f / NPTS);
        smean[tid] = m;
        if (slab && quar == 0 && tid < 3) g_yt3[b*3 + tid] = m;
    }
    __syncthreads();

    const int n = quar*256 + tid;
    const float4* rp = (const float4*)(in + (size_t)n*FDIM);
    float xr[FDIM];
    float4 v0 = rp[0], v1 = rp[1], v2 = rp[2], v3 = rp[3];
    xr[0]=v0.x; xr[1]=v0.y; xr[2]=v0.z; xr[3]=v0.w;
    xr[4]=v1.x; xr[5]=v1.y; xr[6]=v1.z; xr[7]=v1.w;
    xr[8]=v2.x; xr[9]=v2.y; xr[10]=v2.z; xr[11]=v2.w;
    xr[12]=v3.x; xr[13]=v3.y; xr[14]=v3.z; xr[15]=v3.w;
    #pragma unroll
    for (int k = 0; k < FDIM; k++) xr[k] -= smean[k];

    if (!slab) {
        float* p = g_x3 + ((size_t)b*NPTS + n)*3;
        p[0] = xr[0]; p[1] = xr[1]; p[2] = xr[2];
    }

    float z[EDIM];
    #pragma unroll
    for (int e = 0; e < EDIM; e++) {
        float a = sb[e];
        #pragma unroll
        for (int k = 0; k < FDIM; k++) a = fmaf(sW[e*FDIM + k], xr[k], a);
        z[e] = a;
    }

    float t[36];
    #pragma unroll
    for (int e2 = 0; e2 < 36; e2++) {
        float a = sbq[e2];
        #pragma unroll
        for (int e = 0; e < EDIM; e++) a = fmaf(sWq[e2*EDIM + e], z[e], a);
        t[e2] = a;
    }

    #pragma unroll
    for (int h = 0; h < HEADS; h++) {
        const size_t rowi = ((size_t)(s*HEADS + h) * NPTS + n);
        float* qp = g_q_s  + rowi*4;
        float* kp = g_kv_s + rowi*12;
        qp[0] = t[h*3+0]*QSCALE; qp[1] = t[h*3+1]*QSCALE; qp[2] = t[h*3+2]*QSCALE;
        #pragma unroll
        for (int d = 0; d < 3; d++) {
            const float kv = t[12+h*3+d], vv = t[24+h*3+d];
            kp[2*d]   = kv; kp[2*d+1]   = kv;
            kp[6+2*d] = vv; kp[6+2*d+1] = vv;
        }
    }
}

// ============================================================================
// Kernel B/D: attention, split-KV. One block = (bh, qtile, half).
// 128 threads, 2 queries/thread packed as f32x2, 512 keys in 24KB smem.
// Writes UNNORMALIZED partial (o0,o1,o2,l) float4; downstream merges halves.
// CROSS=0: bh=128 -> 1024 blocks; CROSS=1: bh=64 -> 512 blocks.
// ============================================================================
template <int CROSS>
__global__ __launch_bounds__(128) void attn_kernel()
{
    const float* __restrict__ qg  = CROSS ? g_q_c  : g_q_s;
    const float* __restrict__ kvg = CROSS ? g_kv_c : g_kv_s;
    float4*      __restrict__ po  = CROSS ? g_po_c : g_po_s;

    __shared__ float skv[512*12];           // 24 KB duplicated KV (half the keys)
    const int tid  = threadIdx.x;
    const int bh   = blockIdx.x >> 3;
    const int tile = (blockIdx.x >> 1) & 3;
    const int half = blockIdx.x & 1;

    {
        const float4* src = (const float4*)(kvg + (size_t)bh*NPTS*12 + half*512*12);
        float4* dst = (float4*)skv;
        #pragma unroll
        for (int i = 0; i < 512*3/128; i++) dst[tid + i*128] = src[tid + i*128];
    }
    __syncthreads();

    const int n0 = tile*256 + tid;          // query 0
    const int n1 = n0 + 128;                // query 1
    const float* q0p = qg + ((size_t)bh*NPTS + n0)*4;
    const float* q1p = qg + ((size_t)bh*NPTS + n1)*4;
    const u64 q01_0 = pack2(q0p[0], q1p[0]);
    const u64 q01_1 = pack2(q0p[1], q1p[1]);
    const u64 q01_2 = pack2(q0p[2], q1p[2]);

    u64 o0 = 0ull, o1 = 0ull, o2 = 0ull, l = 0ull;   // (0.f,0.f)

    const ulonglong2* kp = (const ulonglong2*)skv;
    #pragma unroll 4
    for (int j = 0; j < 512; j++) {
        const ulonglong2 A = kp[3*j];       // (k0,k0) (k1,k1)
        const ulonglong2 Bq = kp[3*j+1];    // (k2,k2) (v0,v0)
        const ulonglong2 C = kp[3*j+2];     // (v1,v1) (v2,v2)
        u64 s01 = ffma2(q01_0, A.x, ffma2(q01_1, A.y, fmul2(q01_2, Bq.x)));
        float s0, s1; unpack2(s01, s0, s1);
        const u64 p01 = pack2(ex2f(s0), ex2f(s1));
        o0 = ffma2(p01, Bq.y, o0);
        o1 = ffma2(p01, C.x, o1);
        o2 = ffma2(p01, C.y, o2);
        l  = fadd2(l, p01);
    }

    float l0,l1, a00,a10, a01,a11, a02,a12;
    unpack2(l,  l0,  l1);
    unpack2(o0, a00, a10);
    unpack2(o1, a01, a11);
    unpack2(o2, a02, a12);

    float4* dst = po + (size_t)half*(CROSS ? BATCH : BB)*HEADS*NPTS + (size_t)bh*NPTS;
    dst[n0] = make_float4(a00, a01, a02, l0);
    dst[n1] = make_float4(a10, a11, a12, l1);
}

// ============================================================================
// Kernel C: merge self-attn halves, combine heads through Wo_s + bo_s, then
// cross-QKV proj. x-slab rows -> q_c, y-slab rows -> kv_c.
// grid = 128 blocks x 256 threads
// ============================================================================
__global__ __launch_bounds__(256) void combine_qkv_cross(
    const float* __restrict__ Wo_s,   const float* __restrict__ bo_s,
    const float* __restrict__ Wqkv_c, const float* __restrict__ bqkv_c)
{
    __shared__ float sWo[EDIM*EDIM], sbo[EDIM], sWq[36*EDIM], sbq[36];
    const int tid = threadIdx.x;
    for (int i = tid; i < EDIM*EDIM; i += 256) sWo[i] = Wo_s[i];
    if (tid < EDIM) sbo[tid] = bo_s[tid];
    for (int i = tid; i < 36*EDIM; i += 256) sWq[i] = Wqkv_c[i];
    if (tid < 36) sbq[tid] = bqkv_c[tid];
    __syncthreads();

    const int row  = blockIdx.x*256 + tid;      // 0..32767
    const int slab = row >> 14;                 // all rows of a block share slab
    const int b    = (row >> 10) & 15;
    const int n    = row & 1023;
    const int s    = row >> 10;                 // 0..31

    float ohv[EDIM];
    #pragma unroll
    for (int h = 0; h < HEADS; h++) {
        const size_t idx = (size_t)(s*HEADS + h)*NPTS + n;
        const float4 A = g_po_s[idx];
        const float4 Bv = g_po_s[(size_t)BB*HEADS*NPTS + idx];
        const float invl = 1.0f / (A.w + Bv.w);
        ohv[h*3+0] = (A.x + Bv.x) * invl;
        ohv[h*3+1] = (A.y + Bv.y) * invl;
        ohv[h*3+2] = (A.z + Bv.z) * invl;
    }

    float z[EDIM];
    #pragma unroll
    for (int e = 0; e < EDIM; e++) {
        float a = sbo[e];
        #pragma unroll
        for (int k = 0; k < EDIM; k++) a = fmaf(sWo[e*EDIM + k], ohv[k], a);
        z[e] = a;
    }

    if (slab == 0) {
        #pragma unroll
        for (int h = 0; h < HEADS; h++) {
            float* qp = g_q_c + ((size_t)(b*HEADS + h)*NPTS + n)*4;
            #pragma unroll
            for (int d = 0; d < 3; d++) {
                const int e2 = h*3 + d;
                float a = sbq[e2];
                #pragma unroll
                for (int e = 0; e < EDIM; e++) a = fmaf(sWq[e2*EDIM + e], z[e], a);
                qp[d] = a * QSCALE;
            }
        }
    } else {
        #pragma unroll
        for (int h = 0; h < HEADS; h++) {
            float* kp = g_kv_c + ((size_t)(b*HEADS + h)*NPTS + n)*12;
            #pragma unroll
            for (int d = 0; d < 3; d++) {
                const int e2k = 12 + h*3 + d;
                const int e2v = 24 + h*3 + d;
                float ak = sbq[e2k], av = sbq[e2v];
                #pragma unroll
                for (int e = 0; e < EDIM; e++) {
                    ak = fmaf(sWq[e2k*EDIM + e], z[e], ak);
                    av = fmaf(sWq[e2v*EDIM + e], z[e], av);
                }
                kp[2*d]   = ak; kp[2*d+1]   = ak;
                kp[6+2*d] = av; kp[6+2*d+1] = av;
            }
        }
    }
}

// ============================================================================
// Kernel E: merge cross halves, combine heads (Wo_c), project to coords
// (W_out), accumulate partial Kabsch statistics.
// grid = 64 blocks (4 per batch), 256 threads, 1 row/thread.
// ============================================================================
__global__ __launch_bounds__(256) void coords_stats(
    const float* __restrict__ Wo_c,  const float* __restrict__ bo_c,
    const float* __restrict__ W_out, const float* __restrict__ b_out)
{
    __shared__ float sWo[EDIM*EDIM], sbo[EDIM], sWt[3*EDIM], sbt[3];
    __shared__ float sred2[8][15];
    const int tid  = threadIdx.x;
    const int b    = blockIdx.x >> 2;
    const int part = blockIdx.x & 3;
    for (int i = tid; i < EDIM*EDIM; i += 256) sWo[i] = Wo_c[i];
    if (tid < EDIM)   sbo[tid] = bo_c[tid];
    if (tid < 3*EDIM) sWt[tid] = W_out[tid];
    if (tid < 3)      sbt[tid] = b_out[tid];
    __syncthreads();

    const int n = part*256 + tid;
    float ohv[EDIM];
    #pragma unroll
    for (int h = 0; h < HEADS; h++) {
        const size_t idx = (size_t)(b*HEADS + h)*NPTS + n;
        const float4 A = g_po_c[idx];
        const float4 Bv = g_po_c[(size_t)BATCH*HEADS*NPTS + idx];
        const float invl = 1.0f / (A.w + Bv.w);
        ohv[h*3+0] = (A.x + Bv.x) * invl;
        ohv[h*3+1] = (A.y + Bv.y) * invl;
        ohv[h*3+2] = (A.z + Bv.z) * invl;
    }

    float z[EDIM];
    #pragma unroll
    for (int e = 0; e < EDIM; e++) {
        float a = sbo[e];
        #pragma unroll
        for (int k = 0; k < EDIM; k++) a = fmaf(sWo[e*EDIM + k], ohv[k], a);
        z[e] = a;
    }
    float co[3];
    #pragma unroll
    for (int i = 0; i < 3; i++) {
        float a = sbt[i];
        #pragma unroll
        for (int e = 0; e < EDIM; e++) a = fmaf(sWt[i*EDIM + e], z[e], a);
        co[i] = a;
    }
    const float* xp = g_x3 + ((size_t)b*NPTS + n)*3;
    const float x0 = xp[0], x1 = xp[1], x2 = xp[2];
    const float B0 = co[0] + x0, B1 = co[1] + x1, B2 = co[2] + x2;

    float vals[15];
    vals[0]=B0*x0; vals[1]=B0*x1; vals[2]=B0*x2;
    vals[3]=B1*x0; vals[4]=B1*x1; vals[5]=B1*x2;
    vals[6]=B2*x0; vals[7]=B2*x1; vals[8]=B2*x2;
    vals[9]=B0; vals[10]=B1; vals[11]=B2;
    vals[12]=x0; vals[13]=x1; vals[14]=x2;
    #pragma unroll
    for (int k = 0; k < 15; k++) {
        #pragma unroll
        for (int off = 16; off; off >>= 1)
            vals[k] += __shfl_xor_sync(0xffffffffu, vals[k], off);
    }
    const int lane = tid & 31, w = tid >> 5;
    if (lane == 0) {
        #pragma unroll
        for (int k = 0; k < 15; k++) sred2[w][k] = vals[k];
    }
    __syncthreads();
    if (tid < 15) {
        float a = 0.f;
        #pragma unroll
        for (int wi = 0; wi < 8; wi++) a += sred2[wi][tid];
        g_statp[(b*4 + part)*16 + tid] = a;
    }
}

// ============================================================================
// Kernel F: fold partials; Kabsch via Newton polar decomposition.
// Reference: A = coords+x3 (centroid cP), Bp = x3 (centroid cX).
//   H[i][j] = S[j*3+i] - N*cX[i]*cP[j];  R = polar(H);  t = cP - cX @ R
// ============================================================================
__global__ void kabsch_kernel()
{
    const int b = threadIdx.x;
    if (b >= BATCH) return;
    float st[15];
    #pragma unroll
    for (int k = 0; k < 15; k++) {
        float a = 0.f;
        #pragma unroll
        for (int p = 0; p < 4; p++) a += g_statp[(b*4 + p)*16 + k];
        st[k] = a;
    }
    float cP[3] = { st[9]*(1.0f/NPTS),  st[10]*(1.0f/NPTS), st[11]*(1.0f/NPTS) };
    float cX[3] = { st[12]*(1.0f/NPTS), st[13]*(1.0f/NPTS), st[14]*(1.0f/NPTS) };
    float X[9];
    #pragma unroll
    for (int i = 0; i < 3; i++)
        #pragma unroll
        for (int j = 0; j < 3; j++)
            X[i*3+j] = st[j*3+i] - (float)NPTS * cX[i] * cP[j];

    float nf = 0.f;
    #pragma unroll
    for (int k = 0; k < 9; k++) nf += X[k]*X[k];
    const float inv = rsqrtf(nf);
    #pragma unroll
    for (int k = 0; k < 9; k++) X[k] *= inv;

    for (int it = 0; it < 12; it++) {
        float C[9];
        C[0] = X[4]*X[8] - X[5]*X[7];
        C[1] = X[5]*X[6] - X[3]*X[8];
        C[2] = X[3]*X[7] - X[4]*X[6];
        C[3] = X[2]*X[7] - X[1]*X[8];
        C[4] = X[0]*X[8] - X[2]*X[6];
        C[5] = X[1]*X[6] - X[0]*X[7];
        C[6] = X[1]*X[5] - X[2]*X[4];
        C[7] = X[2]*X[3] - X[0]*X[5];
        C[8] = X[0]*X[4] - X[1]*X[3];
        const float det = X[0]*C[0] + X[1]*C[1] + X[2]*C[2];
        const float hid = 0.5f / det;
        #pragma unroll
        for (int k = 0; k < 9; k++) X[k] = 0.5f*X[k] + C[k]*hid;
    }

    float* Rt = g_Rt + b*12;
    #pragma unroll
    for (int k = 0; k < 9; k++) Rt[k] = X[k];
    #pragma unroll
    for (int j = 0; j < 3; j++)
        Rt[9+j] = cP[j] - (cX[0]*X[0*3+j] + cX[1]*X[1*3+j] + cX[2]*X[2*3+j]);
}

// ============================================================================
// Kernel G: out = x3 @ R + t + y_t3     grid = 64 x 256
// ============================================================================
__global__ __launch_bounds__(256) void output_kernel(float* __restrict__ out)
{
    const int row = blockIdx.x*256 + threadIdx.x;   // < 16384
    const int b = row >> 10;
    const float* Rt = g_Rt + b*12;
    const float* yt = g_yt3 + b*3;
    const float* xp = g_x3 + (size_t)row*3;
    const float x0 = xp[0], x1 = xp[1], x2 = xp[2];
    #pragma unroll
    for (int j = 0; j < 3; j++) {
        out[(size_t)row*3 + j] =
            fmaf(x0, Rt[j], fmaf(x1, Rt[3+j], fmaf(x2, Rt[6+j], Rt[9+j] + yt[j])));
    }
}

// ============================================================================
extern "C" void kernel_launch(void* const* d_in, const int* in_sizes, int n_in,
                              void* d_out, int out_size)
{
    (void)in_sizes; (void)n_in; (void)out_size;
    const float* x_orig = (const float*)d_in[0];
    const float* y_orig = (const float*)d_in[1];
    const float* W_in   = (const float*)d_in[2];
    const float* b_in   = (const float*)d_in[3];
    const float* Wqkv_s = (const float*)d_in[4];
    const float* bqkv_s = (const float*)d_in[5];
    const float* Wo_s   = (const float*)d_in[6];
    const float* bo_s   = (const float*)d_in[7];
    const float* Wqkv_c = (const float*)d_in[8];
    const float* bqkv_c = (const float*)d_in[9];
    const float* Wo_c   = (const float*)d_in[10];
    const float* bo_c   = (const float*)d_in[11];
    const float* W_out  = (const float*)d_in[12];
    const float* b_out  = (const float*)d_in[13];
    float* out = (float*)d_out;

    prep_qkv_self<<<BB*4, 256>>>(x_orig, y_orig, W_in, b_in, Wqkv_s, bqkv_s);
    attn_kernel<0><<<BB*HEADS*8, 128>>>();                    // 1024 blocks
    combine_qkv_cross<<<(BB*NPTS)/256, 256>>>(Wo_s, bo_s, Wqkv_c, bqkv_c);
    attn_kernel<1><<<BATCH*HEADS*8, 128>>>();                 // 512 blocks
    coords_stats<<<BATCH*4, 256>>>(Wo_c, bo_c, W_out, b_out);
    kabsch_kernel<<<1, 32>>>();
    output_kernel<<<(BATCH*NPTS)/256, 256>>>(out);
}

// round 7
// speedup vs baseline: 1.6659x; 1.6659x over previous
#include <cuda_runtime.h>
#include <cstdint>

#define BATCH 16
#define NPTS  1024
#define FDIM  16
#define EDIM  12
#define HEADS 4
#define BB    32            // 2*BATCH (x-slab then y-slab)

typedef unsigned long long u64;

// ---------------- scratch (device globals; no allocation allowed) ----------
__device__ float g_x3  [BATCH*NPTS*3];
__device__ float g_yt3 [BATCH*3];
__device__ float g_q_s [BB*HEADS*NPTS*4];       // pre-scaled q (stride 4)
__device__ float g_kv_s[BB*HEADS*NPTS*12];      // duplicated: k0k0 k1k1 k2k2 v0v0 v1v1 v2v2
__device__ float g_q_c [BATCH*HEADS*NPTS*4];
__device__ float g_kv_c[BATCH*HEADS*NPTS*12];
__device__ float4 g_po_s[2*BB*HEADS*NPTS];      // self split-KV partials: o0,o1,o2,l
__device__ float4 g_po_c[4*BATCH*HEADS*NPTS];   // cross split-KV partials (4 pieces)
__device__ float g_statp[BATCH*4*16];           // 4 partial stat sets per batch
__device__ float g_Rt  [BATCH*12];              // R[9], t[3]

__device__ __forceinline__ float ex2f(float x) {
    float y; asm("ex2.approx.ftz.f32 %0, %1;" : "=f"(y) : "f"(x)); return y;
}
__device__ __forceinline__ u64 ffma2(u64 a, u64 b, u64 c) {
    u64 d; asm("fma.rn.f32x2 %0, %1, %2, %3;" : "=l"(d) : "l"(a), "l"(b), "l"(c)); return d;
}
__device__ __forceinline__ u64 fmul2(u64 a, u64 b) {
    u64 d; asm("mul.rn.f32x2 %0, %1, %2;" : "=l"(d) : "l"(a), "l"(b)); return d;
}
__device__ __forceinline__ u64 fadd2(u64 a, u64 b) {
    u64 d; asm("add.rn.f32x2 %0, %1, %2;" : "=l"(d) : "l"(a), "l"(b)); return d;
}
__device__ __forceinline__ u64 pack2(float lo, float hi) {
    u64 d; asm("mov.b64 %0, {%1, %2};" : "=l"(d) : "f"(lo), "f"(hi)); return d;
}
__device__ __forceinline__ void unpack2(u64 v, float& lo, float& hi) {
    asm("mov.b64 {%0, %1}, %2;" : "=f"(lo), "=f"(hi) : "l"(v));
}

// log2(e)/sqrt(3): fold softmax scale + base-2 conversion into Q
#define QSCALE ((float)(1.4426950408889634 / 1.7320508075688772))

// ============================================================================
// Kernel A: per (slab,batch,quarter): column means (redundant per quarter),
// center, input proj, self-QKV proj.  grid = 128 blocks, 256 threads.
// ============================================================================
__global__ __launch_bounds__(256) void prep_qkv_self(
    const float* __restrict__ x_orig, const float* __restrict__ y_orig,
    const float* __restrict__ W_in,   const float* __restrict__ b_in,
    const float* __restrict__ Wqkv_s, const float* __restrict__ bqkv_s)
{
    __shared__ float sW[EDIM*FDIM];
    __shared__ float sb[EDIM];
    __shared__ float sWq[36*EDIM];
    __shared__ float sbq[36];
    __shared__ float sred[256];
    __shared__ float smean[FDIM];

    const int tid  = threadIdx.x;
    const int s    = blockIdx.x >> 2;   // 0..31
    const int quar = blockIdx.x & 3;
    const int slab = s >> 4;            // 0 = x, 1 = y
    const int b    = s & 15;
    const float* in = (slab ? y_orig : x_orig) + (size_t)b * NPTS * FDIM;

    for (int i = tid; i < EDIM*FDIM; i += 256) sW[i]  = W_in[i];
    if (tid < EDIM) sb[tid] = b_in[tid];
    for (int i = tid; i < 36*EDIM;   i += 256) sWq[i] = Wqkv_s[i];
    if (tid < 36)   sbq[tid] = bqkv_s[tid];

    // column sums: thread (seg, f) sums 64 rows
    const int f = tid & 15, seg = tid >> 4;
    float acc = 0.f;
    for (int n = seg*64; n < seg*64 + 64; n++) acc += in[(size_t)n*FDIM + f];
    sred[tid] = acc;
    __syncthreads();
    if (tid < FDIM) {
        float m = 0.f;
        #pragma unroll
        for (int g = 0; g < 16; g++) m += sred[g*16 + tid];
        m *= (1.0f / NPTS);
        smean[tid] = m;
        if (slab && quar == 0 && tid < 3) g_yt3[b*3 + tid] = m;
    }
    __syncthreads();

    const int n = quar*256 + tid;
    const float4* rp = (const float4*)(in + (size_t)n*FDIM);
    float xr[FDIM];
    float4 v0 = rp[0], v1 = rp[1], v2 = rp[2], v3 = rp[3];
    xr[0]=v0.x; xr[1]=v0.y; xr[2]=v0.z; xr[3]=v0.w;
    xr[4]=v1.x; xr[5]=v1.y; xr[6]=v1.z; xr[7]=v1.w;
    xr[8]=v2.x; xr[9]=v2.y; xr[10]=v2.z; xr[11]=v2.w;
    xr[12]=v3.x; xr[13]=v3.y; xr[14]=v3.z; xr[15]=v3.w;
    #pragma unroll
    for (int k = 0; k < FDIM; k++) xr[k] -= smean[k];

    if (!slab) {
        float* p = g_x3 + ((size_t)b*NPTS + n)*3;
        p[0] = xr[0]; p[1] = xr[1]; p[2] = xr[2];
    }

    float z[EDIM];
    #pragma unroll
    for (int e = 0; e < EDIM; e++) {
        float a = sb[e];
        #pragma unroll
        for (int k = 0; k < FDIM; k++) a = fmaf(sW[e*FDIM + k], xr[k], a);
        z[e] = a;
    }

    float t[36];
    #pragma unroll
    for (int e2 = 0; e2 < 36; e2++) {
        float a = sbq[e2];
        #pragma unroll
        for (int e = 0; e < EDIM; e++) a = fmaf(sWq[e2*EDIM + e], z[e], a);
        t[e2] = a;
    }

    #pragma unroll
    for (int h = 0; h < HEADS; h++) {
        const size_t rowi = ((size_t)(s*HEADS + h) * NPTS + n);
        float* qp = g_q_s  + rowi*4;
        float* kp = g_kv_s + rowi*12;
        qp[0] = t[h*3+0]*QSCALE; qp[1] = t[h*3+1]*QSCALE; qp[2] = t[h*3+2]*QSCALE;
        #pragma unroll
        for (int d = 0; d < 3; d++) {
            const float kv = t[12+h*3+d], vv = t[24+h*3+d];
            kp[2*d]   = kv; kp[2*d+1]   = kv;
            kp[6+2*d] = vv; kp[6+2*d+1] = vv;
        }
    }
}

// ============================================================================
// Kernel B/D: attention, split-KV. One block = (bh, qtile, piece).
// 128 threads, 2 queries/thread packed as f32x2.
// Self:  SPLIT=2 (512 keys, 24KB smem) -> 128 bh * 4 * 2 = 1024 blocks
// Cross: SPLIT=4 (256 keys, 12KB smem) ->  64 bh * 4 * 4 = 1024 blocks
// Writes UNNORMALIZED partials (o0,o1,o2,l); downstream merges pieces.
// ============================================================================
template <int CROSS>
__global__ __launch_bounds__(128) void attn_kernel()
{
    constexpr int SPLIT = CROSS ? 4 : 2;
    constexpr int KEYS  = NPTS / SPLIT;
    constexpr int NBH   = (CROSS ? BATCH : BB) * HEADS;

    const float* __restrict__ qg  = CROSS ? g_q_c  : g_q_s;
    const float* __restrict__ kvg = CROSS ? g_kv_c : g_kv_s;
    float4*      __restrict__ po  = CROSS ? g_po_c : g_po_s;

    __shared__ float skv[KEYS*12];
    const int tid   = threadIdx.x;
    const int bh    = blockIdx.x / (4*SPLIT);
    const int rem   = blockIdx.x - bh*(4*SPLIT);
    const int tile  = rem / SPLIT;
    const int piece = rem - tile*SPLIT;

    {
        const float4* src = (const float4*)(kvg + (size_t)bh*NPTS*12 + (size_t)piece*KEYS*12);
        float4* dst = (float4*)skv;
        #pragma unroll
        for (int i = 0; i < KEYS*3/128; i++) dst[tid + i*128] = src[tid + i*128];
    }
    __syncthreads();

    const int n0 = tile*256 + tid;          // query 0
    const int n1 = n0 + 128;                // query 1
    const float* q0p = qg + ((size_t)bh*NPTS + n0)*4;
    const float* q1p = qg + ((size_t)bh*NPTS + n1)*4;
    const u64 q01_0 = pack2(q0p[0], q1p[0]);
    const u64 q01_1 = pack2(q0p[1], q1p[1]);
    const u64 q01_2 = pack2(q0p[2], q1p[2]);

    u64 o0 = 0ull, o1 = 0ull, o2 = 0ull, l = 0ull;   // (0.f,0.f)

    const ulonglong2* kp = (const ulonglong2*)skv;
    #pragma unroll 8
    for (int j = 0; j < KEYS; j++) {
        const ulonglong2 A = kp[3*j];       // (k0,k0) (k1,k1)
        const ulonglong2 Bq = kp[3*j+1];    // (k2,k2) (v0,v0)
        const ulonglong2 C = kp[3*j+2];     // (v1,v1) (v2,v2)
        u64 s01 = ffma2(q01_0, A.x, ffma2(q01_1, A.y, fmul2(q01_2, Bq.x)));
        float s0, s1; unpack2(s01, s0, s1);
        const u64 p01 = pack2(ex2f(s0), ex2f(s1));
        o0 = ffma2(p01, Bq.y, o0);
        o1 = ffma2(p01, C.x, o1);
        o2 = ffma2(p01, C.y, o2);
        l  = fadd2(l, p01);
    }

    float l0,l1, a00,a10, a01,a11, a02,a12;
    unpack2(l,  l0,  l1);
    unpack2(o0, a00, a10);
    unpack2(o1, a01, a11);
    unpack2(o2, a02, a12);

    float4* dst = po + (size_t)piece*NBH*NPTS + (size_t)bh*NPTS;
    dst[n0] = make_float4(a00, a01, a02, l0);
    dst[n1] = make_float4(a10, a11, a12, l1);
}

// ============================================================================
// Kernel C: merge self-attn halves, combine heads through Wo_s + bo_s, then
// cross-QKV proj. x-slab rows -> q_c, y-slab rows -> kv_c.
// grid = 128 blocks x 256 threads
// ============================================================================
__global__ __launch_bounds__(256) void combine_qkv_cross(
    const float* __restrict__ Wo_s,   const float* __restrict__ bo_s,
    const float* __restrict__ Wqkv_c, const float* __restrict__ bqkv_c)
{
    __shared__ float sWo[EDIM*EDIM], sbo[EDIM], sWq[36*EDIM], sbq[36];
    const int tid = threadIdx.x;
    for (int i = tid; i < EDIM*EDIM; i += 256) sWo[i] = Wo_s[i];
    if (tid < EDIM) sbo[tid] = bo_s[tid];
    for (int i = tid; i < 36*EDIM; i += 256) sWq[i] = Wqkv_c[i];
    if (tid < 36) sbq[tid] = bqkv_c[tid];
    __syncthreads();

    const int row  = blockIdx.x*256 + tid;      // 0..32767
    const int slab = row >> 14;                 // all rows of a block share slab
    const int b    = (row >> 10) & 15;
    const int n    = row & 1023;
    const int s    = row >> 10;                 // 0..31

    float ohv[EDIM];
    #pragma unroll
    for (int h = 0; h < HEADS; h++) {
        const size_t idx = (size_t)(s*HEADS + h)*NPTS + n;
        const float4 A = g_po_s[idx];
        const float4 Bv = g_po_s[(size_t)BB*HEADS*NPTS + idx];
        const float invl = 1.0f / (A.w + Bv.w);
        ohv[h*3+0] = (A.x + Bv.x) * invl;
        ohv[h*3+1] = (A.y + Bv.y) * invl;
        ohv[h*3+2] = (A.z + Bv.z) * invl;
    }

    float z[EDIM];
    #pragma unroll
    for (int e = 0; e < EDIM; e++) {
        float a = sbo[e];
        #pragma unroll
        for (int k = 0; k < EDIM; k++) a = fmaf(sWo[e*EDIM + k], ohv[k], a);
        z[e] = a;
    }

    if (slab == 0) {
        #pragma unroll
        for (int h = 0; h < HEADS; h++) {
            float* qp = g_q_c + ((size_t)(b*HEADS + h)*NPTS + n)*4;
            #pragma unroll
            for (int d = 0; d < 3; d++) {
                const int e2 = h*3 + d;
                float a = sbq[e2];
                #pragma unroll
                for (int e = 0; e < EDIM; e++) a = fmaf(sWq[e2*EDIM + e], z[e], a);
                qp[d] = a * QSCALE;
            }
        }
    } else {
        #pragma unroll
        for (int h = 0; h < HEADS; h++) {
            float* kp = g_kv_c + ((size_t)(b*HEADS + h)*NPTS + n)*12;
            #pragma unroll
            for (int d = 0; d < 3; d++) {
                const int e2k = 12 + h*3 + d;
                const int e2v = 24 + h*3 + d;
                float ak = sbq[e2k], av = sbq[e2v];
                #pragma unroll
                for (int e = 0; e < EDIM; e++) {
                    ak = fmaf(sWq[e2k*EDIM + e], z[e], ak);
                    av = fmaf(sWq[e2v*EDIM + e], z[e], av);
                }
                kp[2*d]   = ak; kp[2*d+1]   = ak;
                kp[6+2*d] = av; kp[6+2*d+1] = av;
            }
        }
    }
}

// ============================================================================
// Kernel E: merge 4 cross pieces, combine heads (Wo_c), project to coords
// (W_out), accumulate partial Kabsch statistics.
// grid = 64 blocks (4 per batch), 256 threads, 1 row/thread.
// ============================================================================
__global__ __launch_bounds__(256) void coords_stats(
    const float* __restrict__ Wo_c,  const float* __restrict__ bo_c,
    const float* __restrict__ W_out, const float* __restrict__ b_out)
{
    __shared__ float sWo[EDIM*EDIM], sbo[EDIM], sWt[3*EDIM], sbt[3];
    __shared__ float sred2[8][15];
    const int tid  = threadIdx.x;
    const int b    = blockIdx.x >> 2;
    const int part = blockIdx.x & 3;
    for (int i = tid; i < EDIM*EDIM; i += 256) sWo[i] = Wo_c[i];
    if (tid < EDIM)   sbo[tid] = bo_c[tid];
    if (tid < 3*EDIM) sWt[tid] = W_out[tid];
    if (tid < 3)      sbt[tid] = b_out[tid];
    __syncthreads();

    const int n = part*256 + tid;
    float ohv[EDIM];
    #pragma unroll
    for (int h = 0; h < HEADS; h++) {
        const size_t idx = (size_t)(b*HEADS + h)*NPTS + n;
        float a0 = 0.f, a1 = 0.f, a2 = 0.f, lw = 0.f;
        #pragma unroll
        for (int p = 0; p < 4; p++) {
            const float4 A = g_po_c[(size_t)p*BATCH*HEADS*NPTS + idx];
            a0 += A.x; a1 += A.y; a2 += A.z; lw += A.w;
        }
        const float invl = 1.0f / lw;
        ohv[h*3+0] = a0 * invl;
        ohv[h*3+1] = a1 * invl;
        ohv[h*3+2] = a2 * invl;
    }

    float z[EDIM];
    #pragma unroll
    for (int e = 0; e < EDIM; e++) {
        float a = sbo[e];
        #pragma unroll
        for (int k = 0; k < EDIM; k++) a = fmaf(sWo[e*EDIM + k], ohv[k], a);
        z[e] = a;
    }
    float co[3];
    #pragma unroll
    for (int i = 0; i < 3; i++) {
        float a = sbt[i];
        #pragma unroll
        for (int e = 0; e < EDIM; e++) a = fmaf(sWt[i*EDIM + e], z[e], a);
        co[i] = a;
    }
    const float* xp = g_x3 + ((size_t)b*NPTS + n)*3;
    const float x0 = xp[0], x1 = xp[1], x2 = xp[2];
    const float B0 = co[0] + x0, B1 = co[1] + x1, B2 = co[2] + x2;

    float vals[15];
    vals[0]=B0*x0; vals[1]=B0*x1; vals[2]=B0*x2;
    vals[3]=B1*x0; vals[4]=B1*x1; vals[5]=B1*x2;
    vals[6]=B2*x0; vals[7]=B2*x1; vals[8]=B2*x2;
    vals[9]=B0; vals[10]=B1; vals[11]=B2;
    vals[12]=x0; vals[13]=x1; vals[14]=x2;
    #pragma unroll
    for (int k = 0; k < 15; k++) {
        #pragma unroll
        for (int off = 16; off; off >>= 1)
            vals[k] += __shfl_xor_sync(0xffffffffu, vals[k], off);
    }
    const int lane = tid & 31, w = tid >> 5;
    if (lane == 0) {
        #pragma unroll
        for (int k = 0; k < 15; k++) sred2[w][k] = vals[k];
    }
    __syncthreads();
    if (tid < 15) {
        float a = 0.f;
        #pragma unroll
        for (int wi = 0; wi < 8; wi++) a += sred2[wi][tid];
        g_statp[(b*4 + part)*16 + tid] = a;
    }
}

// ============================================================================
// Kernel F: fold partials; Kabsch via Newton polar decomposition.
// Reference: A = coords+x3 (centroid cP), Bp = x3 (centroid cX).
//   H[i][j] = S[j*3+i] - N*cX[i]*cP[j];  R = polar(H);  t = cP - cX @ R
// ============================================================================
__global__ void kabsch_kernel()
{
    const int b = threadIdx.x;
    if (b >= BATCH) return;
    float st[15];
    #pragma unroll
    for (int k = 0; k < 15; k++) {
        float a = 0.f;
        #pragma unroll
        for (int p = 0; p < 4; p++) a += g_statp[(b*4 + p)*16 + k];
        st[k] = a;
    }
    float cP[3] = { st[9]*(1.0f/NPTS),  st[10]*(1.0f/NPTS), st[11]*(1.0f/NPTS) };
    float cX[3] = { st[12]*(1.0f/NPTS), st[13]*(1.0f/NPTS), st[14]*(1.0f/NPTS) };
    float X[9];
    #pragma unroll
    for (int i = 0; i < 3; i++)
        #pragma unroll
        for (int j = 0; j < 3; j++)
            X[i*3+j] = st[j*3+i] - (float)NPTS * cX[i] * cP[j];

    float nf = 0.f;
    #pragma unroll
    for (int k = 0; k < 9; k++) nf += X[k]*X[k];
    const float inv = rsqrtf(nf);
    #pragma unroll
    for (int k = 0; k < 9; k++) X[k] *= inv;

    for (int it = 0; it < 12; it++) {
        float C[9];
        C[0] = X[4]*X[8] - X[5]*X[7];
        C[1] = X[5]*X[6] - X[3]*X[8];
        C[2] = X[3]*X[7] - X[4]*X[6];
        C[3] = X[2]*X[7] - X[1]*X[8];
        C[4] = X[0]*X[8] - X[2]*X[6];
        C[5] = X[1]*X[6] - X[0]*X[7];
        C[6] = X[1]*X[5] - X[2]*X[4];
        C[7] = X[2]*X[3] - X[0]*X[5];
        C[8] = X[0]*X[4] - X[1]*X[3];
        const float det = X[0]*C[0] + X[1]*C[1] + X[2]*C[2];
        const float hid = 0.5f / det;
        #pragma unroll
        for (int k = 0; k < 9; k++) X[k] = 0.5f*X[k] + C[k]*hid;
    }

    float* Rt = g_Rt + b*12;
    #pragma unroll
    for (int k = 0; k < 9; k++) Rt[k] = X[k];
    #pragma unroll
    for (int j = 0; j < 3; j++)
        Rt[9+j] = cP[j] - (cX[0]*X[0*3+j] + cX[1]*X[1*3+j] + cX[2]*X[2*3+j]);
}

// ============================================================================
// Kernel G: out = x3 @ R + t + y_t3     grid = 64 x 256
// ============================================================================
__global__ __launch_bounds__(256) void output_kernel(float* __restrict__ out)
{
    const int row = blockIdx.x*256 + threadIdx.x;   // < 16384
    const int b = row >> 10;
    const float* Rt = g_Rt + b*12;
    const float* yt = g_yt3 + b*3;
    const float* xp = g_x3 + (size_t)row*3;
    const float x0 = xp[0], x1 = xp[1], x2 = xp[2];
    #pragma unroll
    for (int j = 0; j < 3; j++) {
        out[(size_t)row*3 + j] =
            fmaf(x0, Rt[j], fmaf(x1, Rt[3+j], fmaf(x2, Rt[6+j], Rt[9+j] + yt[j])));
    }
}

// ============================================================================
extern "C" void kernel_launch(void* const* d_in, const int* in_sizes, int n_in,
                              void* d_out, int out_size)
{
    (void)in_sizes; (void)n_in; (void)out_size;
    const float* x_orig = (const float*)d_in[0];
    const float* y_orig = (const float*)d_in[1];
    const float* W_in   = (const float*)d_in[2];
    const float* b_in   = (const float*)d_in[3];
    const float* Wqkv_s = (const float*)d_in[4];
    const float* bqkv_s = (const float*)d_in[5];
    const float* Wo_s   = (const float*)d_in[6];
    const float* bo_s   = (const float*)d_in[7];
    const float* Wqkv_c = (const float*)d_in[8];
    const float* bqkv_c = (const float*)d_in[9];
    const float* Wo_c   = (const float*)d_in[10];
    const float* bo_c   = (const float*)d_in[11];
    const float* W_out  = (const float*)d_in[12];
    const float* b_out  = (const float*)d_in[13];
    float* out = (float*)d_out;

    prep_qkv_self<<<BB*4, 256>>>(x_orig, y_orig, W_in, b_in, Wqkv_s, bqkv_s);
    attn_kernel<0><<<BB*HEADS*4*2, 128>>>();                  // 1024 blocks, SPLIT=2
    combine_qkv_cross<<<(BB*NPTS)/256, 256>>>(Wo_s, bo_s, Wqkv_c, bqkv_c);
    attn_kernel<1><<<BATCH*HEADS*4*4, 128>>>();               // 1024 blocks, SPLIT=4
    coords_stats<<<BATCH*4, 256>>>(Wo_c, bo_c, W_out, b_out);
    kabsch_kernel<<<1, 32>>>();
    output_kernel<<<(BATCH*NPTS)/256, 256>>>(out);
}

// round 8
// speedup vs baseline: 1.7297x; 1.0383x over previous
#include <cuda_runtime.h>
#include <cstdint>

#define BATCH 16
#define NPTS  1024
#define FDIM  16
#define EDIM  12
#define HEADS 4
#define BB    32            // 2*BATCH (x-slab then y-slab)

#define SPLIT_S 8
#define SPLIT_C 16

typedef unsigned long long u64;

// ---------------- scratch (device globals; no allocation allowed) ----------
__device__ float g_x3  [BATCH*NPTS*3];
__device__ float g_yt3 [BATCH*3];
__device__ float g_q_s [BB*HEADS*NPTS*4];       // pre-scaled q (stride 4)
__device__ float g_kv_s[BB*HEADS*NPTS*12];      // duplicated: k0k0 k1k1 k2k2 v0v0 v1v1 v2v2
__device__ float g_q_c [BATCH*HEADS*NPTS*4];
__device__ float g_kv_c[BATCH*HEADS*NPTS*12];
__device__ float4 g_po_s[SPLIT_S*BB*HEADS*NPTS];     // split-KV partials: o0,o1,o2,l
__device__ float4 g_po_c[SPLIT_C*BATCH*HEADS*NPTS];
__device__ float g_statp[BATCH*4*16];           // 4 partial stat sets per batch
__device__ float g_Rt  [BATCH*12];              // R[9], t[3]

__device__ __forceinline__ float ex2f(float x) {
    float y; asm("ex2.approx.ftz.f32 %0, %1;" : "=f"(y) : "f"(x)); return y;
}
__device__ __forceinline__ u64 ffma2(u64 a, u64 b, u64 c) {
    u64 d; asm("fma.rn.f32x2 %0, %1, %2, %3;" : "=l"(d) : "l"(a), "l"(b), "l"(c)); return d;
}
__device__ __forceinline__ u64 fmul2(u64 a, u64 b) {
    u64 d; asm("mul.rn.f32x2 %0, %1, %2;" : "=l"(d) : "l"(a), "l"(b)); return d;
}
__device__ __forceinline__ u64 fadd2(u64 a, u64 b) {
    u64 d; asm("add.rn.f32x2 %0, %1, %2;" : "=l"(d) : "l"(a), "l"(b)); return d;
}
__device__ __forceinline__ u64 pack2(float lo, float hi) {
    u64 d; asm("mov.b64 %0, {%1, %2};" : "=l"(d) : "f"(lo), "f"(hi)); return d;
}
__device__ __forceinline__ void unpack2(u64 v, float& lo, float& hi) {
    asm("mov.b64 {%0, %1}, %2;" : "=f"(lo), "=f"(hi) : "l"(v));
}

// log2(e)/sqrt(3): fold softmax scale + base-2 conversion into Q
#define QSCALE ((float)(1.4426950408889634 / 1.7320508075688772))

// ============================================================================
// Kernel A: per (slab,batch,quarter): column means (redundant per quarter),
// center, input proj, self-QKV proj.  grid = 128 blocks, 256 threads.
// ============================================================================
__global__ __launch_bounds__(256) void prep_qkv_self(
    const float* __restrict__ x_orig, const float* __restrict__ y_orig,
    const float* __restrict__ W_in,   const float* __restrict__ b_in,
    const float* __restrict__ Wqkv_s, const float* __restrict__ bqkv_s)
{
    __shared__ float sW[EDIM*FDIM];
    __shared__ float sb[EDIM];
    __shared__ float sWq[36*EDIM];
    __shared__ float sbq[36];
    __shared__ float sred[256];
    __shared__ float smean[FDIM];

    const int tid  = threadIdx.x;
    const int s    = blockIdx.x >> 2;   // 0..31
    const int quar = blockIdx.x & 3;
    const int slab = s >> 4;            // 0 = x, 1 = y
    const int b    = s & 15;
    const float* in = (slab ? y_orig : x_orig) + (size_t)b * NPTS * FDIM;

    for (int i = tid; i < EDIM*FDIM; i += 256) sW[i]  = W_in[i];
    if (tid < EDIM) sb[tid] = b_in[tid];
    for (int i = tid; i < 36*EDIM;   i += 256) sWq[i] = Wqkv_s[i];
    if (tid < 36)   sbq[tid] = bqkv_s[tid];

    // column sums: thread (seg, f) sums 64 rows
    const int f = tid & 15, seg = tid >> 4;
    float acc = 0.f;
    for (int n = seg*64; n < seg*64 + 64; n++) acc += in[(size_t)n*FDIM + f];
    sred[tid] = acc;
    __syncthreads();
    if (tid < FDIM) {
        float m = 0.f;
        #pragma unroll
        for (int g = 0; g < 16; g++) m += sred[g*16 + tid];
        m *= (1.0f / NPTS);
        smean[tid] = m;
        if (slab && quar == 0 && tid < 3) g_yt3[b*3 + tid] = m;
    }
    __syncthreads();

    const int n = quar*256 + tid;
    const float4* rp = (const float4*)(in + (size_t)n*FDIM);
    float xr[FDIM];
    float4 v0 = rp[0], v1 = rp[1], v2 = rp[2], v3 = rp[3];
    xr[0]=v0.x; xr[1]=v0.y; xr[2]=v0.z; xr[3]=v0.w;
    xr[4]=v1.x; xr[5]=v1.y; xr[6]=v1.z; xr[7]=v1.w;
    xr[8]=v2.x; xr[9]=v2.y; xr[10]=v2.z; xr[11]=v2.w;
    xr[12]=v3.x; xr[13]=v3.y; xr[14]=v3.z; xr[15]=v3.w;
    #pragma unroll
    for (int k = 0; k < FDIM; k++) xr[k] -= smean[k];

    if (!slab) {
        float* p = g_x3 + ((size_t)b*NPTS + n)*3;
        p[0] = xr[0]; p[1] = xr[1]; p[2] = xr[2];
    }

    float z[EDIM];
    #pragma unroll
    for (int e = 0; e < EDIM; e++) {
        float a = sb[e];
        #pragma unroll
        for (int k = 0; k < FDIM; k++) a = fmaf(sW[e*FDIM + k], xr[k], a);
        z[e] = a;
    }

    float t[36];
    #pragma unroll
    for (int e2 = 0; e2 < 36; e2++) {
        float a = sbq[e2];
        #pragma unroll
        for (int e = 0; e < EDIM; e++) a = fmaf(sWq[e2*EDIM + e], z[e], a);
        t[e2] = a;
    }

    #pragma unroll
    for (int h = 0; h < HEADS; h++) {
        const size_t rowi = ((size_t)(s*HEADS + h) * NPTS + n);
        float* qp = g_q_s  + rowi*4;
        float* kp = g_kv_s + rowi*12;
        qp[0] = t[h*3+0]*QSCALE; qp[1] = t[h*3+1]*QSCALE; qp[2] = t[h*3+2]*QSCALE;
        #pragma unroll
        for (int d = 0; d < 3; d++) {
            const float kv = t[12+h*3+d], vv = t[24+h*3+d];
            kp[2*d]   = kv; kp[2*d+1]   = kv;
            kp[6+2*d] = vv; kp[6+2*d+1] = vv;
        }
    }
}

// ============================================================================
// Kernel B/D: attention, split-KV, 4 queries/thread (2 f32x2 packs).
// One block = (bh, qtile(2), piece(SPLIT)).  128 threads.
// Self:  SPLIT=8,  KEYS=128, 6KB smem  -> 128*2*8  = 2048 blocks
// Cross: SPLIT=16, KEYS=64,  3KB smem  ->  64*2*16 = 2048 blocks
// Writes UNNORMALIZED partials (o0,o1,o2,l); downstream merges pieces.
// ============================================================================
template <int CROSS>
__global__ __launch_bounds__(128) void attn_kernel()
{
    constexpr int SPLIT = CROSS ? SPLIT_C : SPLIT_S;
    constexpr int KEYS  = NPTS / SPLIT;
    constexpr int NBH   = (CROSS ? BATCH : BB) * HEADS;

    const float* __restrict__ qg  = CROSS ? g_q_c  : g_q_s;
    const float* __restrict__ kvg = CROSS ? g_kv_c : g_kv_s;
    float4*      __restrict__ po  = CROSS ? g_po_c : g_po_s;

    __shared__ float skv[KEYS*12];
    const int tid   = threadIdx.x;
    const int bh    = blockIdx.x / (2*SPLIT);
    const int rem   = blockIdx.x - bh*(2*SPLIT);
    const int tile  = rem / SPLIT;
    const int piece = rem - tile*SPLIT;

    {
        const float4* src = (const float4*)(kvg + (size_t)bh*NPTS*12 + (size_t)piece*KEYS*12);
        float4* dst = (float4*)skv;
        for (int i = tid; i < KEYS*3; i += 128) dst[i] = src[i];
    }
    __syncthreads();

    const int n0 = tile*512 + tid;          // queries n0, n0+128, n0+256, n0+384
    const float* qp0 = qg + ((size_t)bh*NPTS + n0)*4;
    const float* qp1 = qp0 + 128*4;
    const float* qp2 = qp0 + 256*4;
    const float* qp3 = qp0 + 384*4;
    const u64 qa0 = pack2(qp0[0], qp1[0]);
    const u64 qa1 = pack2(qp0[1], qp1[1]);
    const u64 qa2 = pack2(qp0[2], qp1[2]);
    const u64 qb0 = pack2(qp2[0], qp3[0]);
    const u64 qb1 = pack2(qp2[1], qp3[1]);
    const u64 qb2 = pack2(qp2[2], qp3[2]);

    u64 oa0=0ull, oa1=0ull, oa2=0ull, la=0ull;
    u64 ob0=0ull, ob1=0ull, ob2=0ull, lb=0ull;

    const ulonglong2* kp = (const ulonglong2*)skv;
    #pragma unroll 4
    for (int j = 0; j < KEYS; j++) {
        const ulonglong2 A  = kp[3*j];      // (k0,k0) (k1,k1)
        const ulonglong2 Bq = kp[3*j+1];    // (k2,k2) (v0,v0)
        const ulonglong2 C  = kp[3*j+2];    // (v1,v1) (v2,v2)
        const u64 sa = ffma2(qa0, A.x, ffma2(qa1, A.y, fmul2(qa2, Bq.x)));
        const u64 sb = ffma2(qb0, A.x, ffma2(qb1, A.y, fmul2(qb2, Bq.x)));
        float s0,s1,s2,s3;
        unpack2(sa, s0, s1);
        unpack2(sb, s2, s3);
        const u64 pA = pack2(ex2f(s0), ex2f(s1));
        const u64 pB = pack2(ex2f(s2), ex2f(s3));
        oa0 = ffma2(pA, Bq.y, oa0); oa1 = ffma2(pA, C.x, oa1);
        oa2 = ffma2(pA, C.y, oa2); la  = fadd2(la, pA);
        ob0 = ffma2(pB, Bq.y, ob0); ob1 = ffma2(pB, C.x, ob1);
        ob2 = ffma2(pB, C.y, ob2); lb  = fadd2(lb, pB);
    }

    float4* dst = po + (size_t)piece*NBH*NPTS + (size_t)bh*NPTS;
    {
        float l0,l1, x0,x1, y0,y1, z0,z1;
        unpack2(la, l0, l1); unpack2(oa0, x0, x1);
        unpack2(oa1, y0, y1); unpack2(oa2, z0, z1);
        dst[n0]       = make_float4(x0, y0, z0, l0);
        dst[n0 + 128] = make_float4(x1, y1, z1, l1);
        unpack2(lb, l0, l1); unpack2(ob0, x0, x1);
        unpack2(ob1, y0, y1); unpack2(ob2, z0, z1);
        dst[n0 + 256] = make_float4(x0, y0, z0, l0);
        dst[n0 + 384] = make_float4(x1, y1, z1, l1);
    }
}

// ============================================================================
// Kernel C: merge SPLIT_S self-attn pieces, combine heads through Wo_s + bo_s,
// then cross-QKV proj. x-slab rows -> q_c, y-slab rows -> kv_c.
// grid = 128 blocks x 256 threads
// ============================================================================
__global__ __launch_bounds__(256) void combine_qkv_cross(
    const float* __restrict__ Wo_s,   const float* __restrict__ bo_s,
    const float* __restrict__ Wqkv_c, const float* __restrict__ bqkv_c)
{
    __shared__ float sWo[EDIM*EDIM], sbo[EDIM], sWq[36*EDIM], sbq[36];
    const int tid = threadIdx.x;
    for (int i = tid; i < EDIM*EDIM; i += 256) sWo[i] = Wo_s[i];
    if (tid < EDIM) sbo[tid] = bo_s[tid];
    for (int i = tid; i < 36*EDIM; i += 256) sWq[i] = Wqkv_c[i];
    if (tid < 36) sbq[tid] = bqkv_c[tid];
    __syncthreads();

    const int row  = blockIdx.x*256 + tid;      // 0..32767
    const int slab = row >> 14;                 // all rows of a block share slab
    const int b    = (row >> 10) & 15;
    const int n    = row & 1023;
    const int s    = row >> 10;                 // 0..31

    float ohv[EDIM];
    #pragma unroll
    for (int h = 0; h < HEADS; h++) {
        const size_t idx = (size_t)(s*HEADS + h)*NPTS + n;
        float a0 = 0.f, a1 = 0.f, a2 = 0.f, lw = 0.f;
        #pragma unroll
        for (int p = 0; p < SPLIT_S; p++) {
            const float4 A = g_po_s[(size_t)p*BB*HEADS*NPTS + idx];
            a0 += A.x; a1 += A.y; a2 += A.z; lw += A.w;
        }
        const float invl = 1.0f / lw;
        ohv[h*3+0] = a0 * invl;
        ohv[h*3+1] = a1 * invl;
        ohv[h*3+2] = a2 * invl;
    }

    float z[EDIM];
    #pragma unroll
    for (int e = 0; e < EDIM; e++) {
        float a = sbo[e];
        #pragma unroll
        for (int k = 0; k < EDIM; k++) a = fmaf(sWo[e*EDIM + k], ohv[k], a);
        z[e] = a;
    }

    if (slab == 0) {
        #pragma unroll
        for (int h = 0; h < HEADS; h++) {
            float* qp = g_q_c + ((size_t)(b*HEADS + h)*NPTS + n)*4;
            #pragma unroll
            for (int d = 0; d < 3; d++) {
                const int e2 = h*3 + d;
                float a = sbq[e2];
                #pragma unroll
                for (int e = 0; e < EDIM; e++) a = fmaf(sWq[e2*EDIM + e], z[e], a);
                qp[d] = a * QSCALE;
            }
        }
    } else {
        #pragma unroll
        for (int h = 0; h < HEADS; h++) {
            float* kp = g_kv_c + ((size_t)(b*HEADS + h)*NPTS + n)*12;
            #pragma unroll
            for (int d = 0; d < 3; d++) {
                const int e2k = 12 + h*3 + d;
                const int e2v = 24 + h*3 + d;
                float ak = sbq[e2k], av = sbq[e2v];
                #pragma unroll
                for (int e = 0; e < EDIM; e++) {
                    ak = fmaf(sWq[e2k*EDIM + e], z[e], ak);
                    av = fmaf(sWq[e2v*EDIM + e], z[e], av);
                }
                kp[2*d]   = ak; kp[2*d+1]   = ak;
                kp[6+2*d] = av; kp[6+2*d+1] = av;
            }
        }
    }
}

// ============================================================================
// Kernel E: merge SPLIT_C cross pieces, combine heads (Wo_c), project to
// coords (W_out), accumulate partial Kabsch statistics.
// grid = 64 blocks (4 per batch), 256 threads, 1 row/thread.
// ============================================================================
__global__ __launch_bounds__(256) void coords_stats(
    const float* __restrict__ Wo_c,  const float* __restrict__ bo_c,
    const float* __restrict__ W_out, const float* __restrict__ b_out)
{
    __shared__ float sWo[EDIM*EDIM], sbo[EDIM], sWt[3*EDIM], sbt[3];
    __shared__ float sred2[8][15];
    const int tid  = threadIdx.x;
    const int b    = blockIdx.x >> 2;
    const int part = blockIdx.x & 3;
    for (int i = tid; i < EDIM*EDIM; i += 256) sWo[i] = Wo_c[i];
    if (tid < EDIM)   sbo[tid] = bo_c[tid];
    if (tid < 3*EDIM) sWt[tid] = W_out[tid];
    if (tid < 3)      sbt[tid] = b_out[tid];
    __syncthreads();

    const int n = part*256 + tid;
    float ohv[EDIM];
    #pragma unroll
    for (int h = 0; h < HEADS; h++) {
        const size_t idx = (size_t)(b*HEADS + h)*NPTS + n;
        float a0 = 0.f, a1 = 0.f, a2 = 0.f, lw = 0.f;
        #pragma unroll
        for (int p = 0; p < SPLIT_C; p++) {
            const float4 A = g_po_c[(size_t)p*BATCH*HEADS*NPTS + idx];
            a0 += A.x; a1 += A.y; a2 += A.z; lw += A.w;
        }
        const float invl = 1.0f / lw;
        ohv[h*3+0] = a0 * invl;
        ohv[h*3+1] = a1 * invl;
        ohv[h*3+2] = a2 * invl;
    }

    float z[EDIM];
    #pragma unroll
    for (int e = 0; e < EDIM; e++) {
        float a = sbo[e];
        #pragma unroll
        for (int k = 0; k < EDIM; k++) a = fmaf(sWo[e*EDIM + k], ohv[k], a);
        z[e] = a;
    }
    float co[3];
    #pragma unroll
    for (int i = 0; i < 3; i++) {
        float a = sbt[i];
        #pragma unroll
        for (int e = 0; e < EDIM; e++) a = fmaf(sWt[i*EDIM + e], z[e], a);
        co[i] = a;
    }
    const float* xp = g_x3 + ((size_t)b*NPTS + n)*3;
    const float x0 = xp[0], x1 = xp[1], x2 = xp[2];
    const float B0 = co[0] + x0, B1 = co[1] + x1, B2 = co[2] + x2;

    float vals[15];
    vals[0]=B0*x0; vals[1]=B0*x1; vals[2]=B0*x2;
    vals[3]=B1*x0; vals[4]=B1*x1; vals[5]=B1*x2;
    vals[6]=B2*x0; vals[7]=B2*x1; vals[8]=B2*x2;
    vals[9]=B0; vals[10]=B1; vals[11]=B2;
    vals[12]=x0; vals[13]=x1; vals[14]=x2;
    #pragma unroll
    for (int k = 0; k < 15; k++) {
        #pragma unroll
        for (int off = 16; off; off >>= 1)
            vals[k] += __shfl_xor_sync(0xffffffffu, vals[k], off);
    }
    const int lane = tid & 31, w = tid >> 5;
    if (lane == 0) {
        #pragma unroll
        for (int k = 0; k < 15; k++) sred2[w][k] = vals[k];
    }
    __syncthreads();
    if (tid < 15) {
        float a = 0.f;
        #pragma unroll
        for (int wi = 0; wi < 8; wi++) a += sred2[wi][tid];
        g_statp[(b*4 + part)*16 + tid] = a;
    }
}

// ============================================================================
// Kernel F: fold partials; Kabsch via Newton polar decomposition.
// Reference: A = coords+x3 (centroid cP), Bp = x3 (centroid cX).
//   H[i][j] = S[j*3+i] - N*cX[i]*cP[j];  R = polar(H);  t = cP - cX @ R
// ============================================================================
__global__ void kabsch_kernel()
{
    const int b = threadIdx.x;
    if (b >= BATCH) return;
    float st[15];
    #pragma unroll
    for (int k = 0; k < 15; k++) {
        float a = 0.f;
        #pragma unroll
        for (int p = 0; p < 4; p++) a += g_statp[(b*4 + p)*16 + k];
        st[k] = a;
    }
    float cP[3] = { st[9]*(1.0f/NPTS),  st[10]*(1.0f/NPTS), st[11]*(1.0f/NPTS) };
    float cX[3] = { st[12]*(1.0f/NPTS), st[13]*(1.0f/NPTS), st[14]*(1.0f/NPTS) };
    float X[9];
    #pragma unroll
    for (int i = 0; i < 3; i++)
        #pragma unroll
        for (int j = 0; j < 3; j++)
            X[i*3+j] = st[j*3+i] - (float)NPTS * cX[i] * cP[j];

    float nf = 0.f;
    #pragma unroll
    for (int k = 0; k < 9; k++) nf += X[k]*X[k];
    const float inv = rsqrtf(nf);
    #pragma unroll
    for (int k = 0; k < 9; k++) X[k] *= inv;

    for (int it = 0; it < 12; it++) {
        float C[9];
        C[0] = X[4]*X[8] - X[5]*X[7];
        C[1] = X[5]*X[6] - X[3]*X[8];
        C[2] = X[3]*X[7] - X[4]*X[6];
        C[3] = X[2]*X[7] - X[1]*X[8];
        C[4] = X[0]*X[8] - X[2]*X[6];
        C[5] = X[1]*X[6] - X[0]*X[7];
        C[6] = X[1]*X[5] - X[2]*X[4];
        C[7] = X[2]*X[3] - X[0]*X[5];
        C[8] = X[0]*X[4] - X[1]*X[3];
        const float det = X[0]*C[0] + X[1]*C[1] + X[2]*C[2];
        const float hid = 0.5f / det;
        #pragma unroll
        for (int k = 0; k < 9; k++) X[k] = 0.5f*X[k] + C[k]*hid;
    }

    float* Rt = g_Rt + b*12;
    #pragma unroll
    for (int k = 0; k < 9; k++) Rt[k] = X[k];
    #pragma unroll
    for (int j = 0; j < 3; j++)
        Rt[9+j] = cP[j] - (cX[0]*X[0*3+j] + cX[1]*X[1*3+j] + cX[2]*X[2*3+j]);
}

// ============================================================================
// Kernel G: out = x3 @ R + t + y_t3     grid = 64 x 256
// ============================================================================
__global__ __launch_bounds__(256) void output_kernel(float* __restrict__ out)
{
    const int row = blockIdx.x*256 + threadIdx.x;   // < 16384
    const int b = row >> 10;
    const float* Rt = g_Rt + b*12;
    const float* yt = g_yt3 + b*3;
    const float* xp = g_x3 + (size_t)row*3;
    const float x0 = xp[0], x1 = xp[1], x2 = xp[2];
    #pragma unroll
    for (int j = 0; j < 3; j++) {
        out[(size_t)row*3 + j] =
            fmaf(x0, Rt[j], fmaf(x1, Rt[3+j], fmaf(x2, Rt[6+j], Rt[9+j] + yt[j])));
    }
}

// ============================================================================
extern "C" void kernel_launch(void* const* d_in, const int* in_sizes, int n_in,
                              void* d_out, int out_size)
{
    (void)in_sizes; (void)n_in; (void)out_size;
    const float* x_orig = (const float*)d_in[0];
    const float* y_orig = (const float*)d_in[1];
    const float* W_in   = (const float*)d_in[2];
    const float* b_in   = (const float*)d_in[3];
    const float* Wqkv_s = (const float*)d_in[4];
    const float* bqkv_s = (const float*)d_in[5];
    const float* Wo_s   = (const float*)d_in[6];
    const float* bo_s   = (const float*)d_in[7];
    const float* Wqkv_c = (const float*)d_in[8];
    const float* bqkv_c = (const float*)d_in[9];
    const float* Wo_c   = (const float*)d_in[10];
    const float* bo_c   = (const float*)d_in[11];
    const float* W_out  = (const float*)d_in[12];
    const float* b_out  = (const float*)d_in[13];
    float* out = (float*)d_out;

    prep_qkv_self<<<BB*4, 256>>>(x_orig, y_orig, W_in, b_in, Wqkv_s, bqkv_s);
    attn_kernel<0><<<BB*HEADS*2*SPLIT_S, 128>>>();            // 2048 blocks
    combine_qkv_cross<<<(BB*NPTS)/256, 256>>>(Wo_s, bo_s, Wqkv_c, bqkv_c);
    attn_kernel<1><<<BATCH*HEADS*2*SPLIT_C, 128>>>();         // 2048 blocks
    coords_stats<<<BATCH*4, 256>>>(Wo_c, bo_c, W_out, b_out);
    kabsch_kernel<<<1, 32>>>();
    output_kernel<<<(BATCH*NPTS)/256, 256>>>(out);
}

// round 10
// speedup vs baseline: 1.7654x; 1.0207x over previous
#include <cuda_runtime.h>
#include <cstdint>

#define BATCH 16
#define NPTS  1024
#define FDIM  16
#define EDIM  12
#define HEADS 4
#define BB    32            // 2*BATCH (x-slab then y-slab)

#define SPLIT_S 8
#define SPLIT_C 16

typedef unsigned long long u64;

// ---------------- scratch (device globals; no allocation allowed) ----------
__device__ float g_x3  [BATCH*NPTS*3];
__device__ float g_yt3 [BATCH*3];
__device__ float g_q_s [BB*HEADS*NPTS*4];       // pre-scaled q (stride 4)
__device__ float g_kv_s[BB*HEADS*NPTS*12];      // duplicated: k0k0 k1k1 k2k2 v0v0 v1v1 v2v2
__device__ float g_q_c [BATCH*HEADS*NPTS*4];
__device__ float g_kv_c[BATCH*HEADS*NPTS*12];
__device__ float4 g_po_s[SPLIT_S*BB*HEADS*NPTS];     // split-KV partials: o0,o1,o2,l
__device__ float4 g_po_c[SPLIT_C*BATCH*HEADS*NPTS];
__device__ float g_statp[BATCH*4*16];           // 4 partial stat sets per batch

__device__ __forceinline__ float ex2f(float x) {
    float y; asm("ex2.approx.ftz.f32 %0, %1;" : "=f"(y) : "f"(x)); return y;
}
__device__ __forceinline__ u64 ffma2(u64 a, u64 b, u64 c) {
    u64 d; asm("fma.rn.f32x2 %0, %1, %2, %3;" : "=l"(d) : "l"(a), "l"(b), "l"(c)); return d;
}
__device__ __forceinline__ u64 fmul2(u64 a, u64 b) {
    u64 d; asm("mul.rn.f32x2 %0, %1, %2;" : "=l"(d) : "l"(a), "l"(b)); return d;
}
__device__ __forceinline__ u64 fadd2(u64 a, u64 b) {
    u64 d; asm("add.rn.f32x2 %0, %1, %2;" : "=l"(d) : "l"(a), "l"(b)); return d;
}
__device__ __forceinline__ u64 pack2(float lo, float hi) {
    u64 d; asm("mov.b64 %0, {%1, %2};" : "=l"(d) : "f"(lo), "f"(hi)); return d;
}
__device__ __forceinline__ void unpack2(u64 v, float& lo, float& hi) {
    asm("mov.b64 {%0, %1}, %2;" : "=f"(lo), "=f"(hi) : "l"(v));
}

// log2(e)/sqrt(3): fold softmax scale + base-2 conversion into Q
#define QSCALE ((float)(1.4426950408889634 / 1.7320508075688772))

// ============================================================================
// Kernel A: per (slab,batch,quarter): column means (redundant per quarter),
// center, input proj, self-QKV proj.  grid = 128 blocks, 256 threads.
// ============================================================================
__global__ __launch_bounds__(256) void prep_qkv_self(
    const float* __restrict__ x_orig, const float* __restrict__ y_orig,
    const float* __restrict__ W_in,   const float* __restrict__ b_in,
    const float* __restrict__ Wqkv_s, const float* __restrict__ bqkv_s)
{
    __shared__ float sW[EDIM*FDIM];
    __shared__ float sb[EDIM];
    __shared__ float sWq[36*EDIM];
    __shared__ float sbq[36];
    __shared__ float sred[256];
    __shared__ float smean[FDIM];

    const int tid  = threadIdx.x;
    const int s    = blockIdx.x >> 2;   // 0..31
    const int quar = blockIdx.x & 3;
    const int slab = s >> 4;            // 0 = x, 1 = y
    const int b    = s & 15;
    const float* in = (slab ? y_orig : x_orig) + (size_t)b * NPTS * FDIM;

    for (int i = tid; i < EDIM*FDIM; i += 256) sW[i]  = W_in[i];
    if (tid < EDIM) sb[tid] = b_in[tid];
    for (int i = tid; i < 36*EDIM;   i += 256) sWq[i] = Wqkv_s[i];
    if (tid < 36)   sbq[tid] = bqkv_s[tid];

    // column sums: thread (seg, f) sums 64 rows
    const int f = tid & 15, seg = tid >> 4;
    float acc = 0.f;
    for (int n = seg*64; n < seg*64 + 64; n++) acc += in[(size_t)n*FDIM + f];
    sred[tid] = acc;
    __syncthreads();
    if (tid < FDIM) {
        float m = 0.f;
        #pragma unroll
        for (int g = 0; g < 16; g++) m += sred[g*16 + tid];
        m *= (1.0f / NPTS);
        smean[tid] = m;
        if (slab && quar == 0 && tid < 3) g_yt3[b*3 + tid] = m;
    }
    __syncthreads();

    const int n = quar*256 + tid;
    const float4* rp = (const float4*)(in + (size_t)n*FDIM);
    float xr[FDIM];
    float4 v0 = rp[0], v1 = rp[1], v2 = rp[2], v3 = rp[3];
    xr[0]=v0.x; xr[1]=v0.y; xr[2]=v0.z; xr[3]=v0.w;
    xr[4]=v1.x; xr[5]=v1.y; xr[6]=v1.z; xr[7]=v1.w;
    xr[8]=v2.x; xr[9]=v2.y; xr[10]=v2.z; xr[11]=v2.w;
    xr[12]=v3.x; xr[13]=v3.y; xr[14]=v3.z; xr[15]=v3.w;
    #pragma unroll
    for (int k = 0; k < FDIM; k++) xr[k] -= smean[k];

    if (!slab) {
        float* p = g_x3 + ((size_t)b*NPTS + n)*3;
        p[0] = xr[0]; p[1] = xr[1]; p[2] = xr[2];
    }

    float z[EDIM];
    #pragma unroll
    for (int e = 0; e < EDIM; e++) {
        float a = sb[e];
        #pragma unroll
        for (int k = 0; k < FDIM; k++) a = fmaf(sW[e*FDIM + k], xr[k], a);
        z[e] = a;
    }

    float t[36];
    #pragma unroll
    for (int e2 = 0; e2 < 36; e2++) {
        float a = sbq[e2];
        #pragma unroll
        for (int e = 0; e < EDIM; e++) a = fmaf(sWq[e2*EDIM + e], z[e], a);
        t[e2] = a;
    }

    #pragma unroll
    for (int h = 0; h < HEADS; h++) {
        const size_t rowi = ((size_t)(s*HEADS + h) * NPTS + n);
        float* qp = g_q_s  + rowi*4;
        float* kp = g_kv_s + rowi*12;
        qp[0] = t[h*3+0]*QSCALE; qp[1] = t[h*3+1]*QSCALE; qp[2] = t[h*3+2]*QSCALE;
        #pragma unroll
        for (int d = 0; d < 3; d++) {
            const float kv = t[12+h*3+d], vv = t[24+h*3+d];
            kp[2*d]   = kv; kp[2*d+1]   = kv;
            kp[6+2*d] = vv; kp[6+2*d+1] = vv;
        }
    }
}

// ============================================================================
// Kernel B/D: attention, split-KV, 8 queries/thread (4 f32x2 packs).
// One block = (bh, piece).  128 threads cover all 1024 queries.
// Self:  SPLIT=8,  KEYS=128, 6KB smem -> 128*8  = 1024 blocks
// Cross: SPLIT=16, KEYS=64,  3KB smem ->  64*16 = 1024 blocks
// Writes UNNORMALIZED partials (o0,o1,o2,l); downstream merges pieces.
// ============================================================================
template <int CROSS>
__global__ __launch_bounds__(128) void attn_kernel()
{
    constexpr int SPLIT = CROSS ? SPLIT_C : SPLIT_S;
    constexpr int KEYS  = NPTS / SPLIT;
    constexpr int NBH   = (CROSS ? BATCH : BB) * HEADS;

    const float* __restrict__ qg  = CROSS ? g_q_c  : g_q_s;
    const float* __restrict__ kvg = CROSS ? g_kv_c : g_kv_s;
    float4*      __restrict__ po  = CROSS ? g_po_c : g_po_s;

    __shared__ float skv[KEYS*12];
    const int tid   = threadIdx.x;
    const int bh    = blockIdx.x / SPLIT;
    const int piece = blockIdx.x - bh*SPLIT;

    {
        const float4* src = (const float4*)(kvg + (size_t)bh*NPTS*12 + (size_t)piece*KEYS*12);
        float4* dst = (float4*)skv;
        for (int i = tid; i < KEYS*3; i += 128) dst[i] = src[i];
    }
    __syncthreads();

    // queries: tid + 128*k, k = 0..7, packed in pairs (k, k+1)
    const float* qp = qg + ((size_t)bh*NPTS + tid)*4;
    u64 q0[4], q1[4], q2[4];
    #pragma unroll
    for (int p = 0; p < 4; p++) {
        const float* qA = qp + (2*p)  *128*4;
        const float* qB = qp + (2*p+1)*128*4;
        q0[p] = pack2(qA[0], qB[0]);
        q1[p] = pack2(qA[1], qB[1]);
        q2[p] = pack2(qA[2], qB[2]);
    }

    u64 o0[4] = {0,0,0,0}, o1[4] = {0,0,0,0}, o2[4] = {0,0,0,0}, lw[4] = {0,0,0,0};

    const ulonglong2* kp = (const ulonglong2*)skv;
    #pragma unroll 4
    for (int j = 0; j < KEYS; j++) {
        const ulonglong2 A  = kp[3*j];      // (k0,k0) (k1,k1)
        const ulonglong2 Bq = kp[3*j+1];    // (k2,k2) (v0,v0)
        const ulonglong2 C  = kp[3*j+2];    // (v1,v1) (v2,v2)
        #pragma unroll
        for (int p = 0; p < 4; p++) {
            const u64 s = ffma2(q0[p], A.x, ffma2(q1[p], A.y, fmul2(q2[p], Bq.x)));
            float s0, s1; unpack2(s, s0, s1);
            const u64 pr = pack2(ex2f(s0), ex2f(s1));
            o0[p] = ffma2(pr, Bq.y, o0[p]);
            o1[p] = ffma2(pr, C.x,  o1[p]);
            o2[p] = ffma2(pr, C.y,  o2[p]);
            lw[p] = fadd2(lw[p], pr);
        }
    }

    float4* dst = po + (size_t)piece*NBH*NPTS + (size_t)bh*NPTS + tid;
    #pragma unroll
    for (int p = 0; p < 4; p++) {
        float l0,l1, x0,x1, y0,y1, z0,z1;
        unpack2(lw[p], l0, l1);
        unpack2(o0[p], x0, x1);
        unpack2(o1[p], y0, y1);
        unpack2(o2[p], z0, z1);
        dst[(2*p)  *128] = make_float4(x0, y0, z0, l0);
        dst[(2*p+1)*128] = make_float4(x1, y1, z1, l1);
    }
}

// ============================================================================
// Kernel C: merge SPLIT_S self-attn pieces, combine heads through Wo_s + bo_s,
// then cross-QKV proj. x-slab rows -> q_c, y-slab rows -> kv_c.
// grid = 128 blocks x 256 threads
// ============================================================================
__global__ __launch_bounds__(256) void combine_qkv_cross(
    const float* __restrict__ Wo_s,   const float* __restrict__ bo_s,
    const float* __restrict__ Wqkv_c, const float* __restrict__ bqkv_c)
{
    __shared__ float sWo[EDIM*EDIM], sbo[EDIM], sWq[36*EDIM], sbq[36];
    const int tid = threadIdx.x;
    for (int i = tid; i < EDIM*EDIM; i += 256) sWo[i] = Wo_s[i];
    if (tid < EDIM) sbo[tid] = bo_s[tid];
    for (int i = tid; i < 36*EDIM; i += 256) sWq[i] = Wqkv_c[i];
    if (tid < 36) sbq[tid] = bqkv_c[tid];
    __syncthreads();

    const int row  = blockIdx.x*256 + tid;      // 0..32767
    const int slab = row >> 14;                 // all rows of a block share slab
    const int b    = (row >> 10) & 15;
    const int n    = row & 1023;
    const int s    = row >> 10;                 // 0..31

    float ohv[EDIM];
    #pragma unroll
    for (int h = 0; h < HEADS; h++) {
        const size_t idx = (size_t)(s*HEADS + h)*NPTS + n;
        float a0 = 0.f, a1 = 0.f, a2 = 0.f, lw = 0.f;
        #pragma unroll
        for (int p = 0; p < SPLIT_S; p++) {
            const float4 A = g_po_s[(size_t)p*BB*HEADS*NPTS + idx];
            a0 += A.x; a1 += A.y; a2 += A.z; lw += A.w;
        }
        const float invl = 1.0f / lw;
        ohv[h*3+0] = a0 * invl;
        ohv[h*3+1] = a1 * invl;
        ohv[h*3+2] = a2 * invl;
    }

    float z[EDIM];
    #pragma unroll
    for (int e = 0; e < EDIM; e++) {
        float a = sbo[e];
        #pragma unroll
        for (int k = 0; k < EDIM; k++) a = fmaf(sWo[e*EDIM + k], ohv[k], a);
        z[e] = a;
    }

    if (slab == 0) {
        #pragma unroll
        for (int h = 0; h < HEADS; h++) {
            float* qp = g_q_c + ((size_t)(b*HEADS + h)*NPTS + n)*4;
            #pragma unroll
            for (int d = 0; d < 3; d++) {
                const int e2 = h*3 + d;
                float a = sbq[e2];
                #pragma unroll
                for (int e = 0; e < EDIM; e++) a = fmaf(sWq[e2*EDIM + e], z[e], a);
                qp[d] = a * QSCALE;
            }
        }
    } else {
        #pragma unroll
        for (int h = 0; h < HEADS; h++) {
            float* kp = g_kv_c + ((size_t)(b*HEADS + h)*NPTS + n)*12;
            #pragma unroll
            for (int d = 0; d < 3; d++) {
                const int e2k = 12 + h*3 + d;
                const int e2v = 24 + h*3 + d;
                float ak = sbq[e2k], av = sbq[e2v];
                #pragma unroll
                for (int e = 0; e < EDIM; e++) {
                    ak = fmaf(sWq[e2k*EDIM + e], z[e], ak);
                    av = fmaf(sWq[e2v*EDIM + e], z[e], av);
                }
                kp[2*d]   = ak; kp[2*d+1]   = ak;
                kp[6+2*d] = av; kp[6+2*d+1] = av;
            }
        }
    }
}

// ============================================================================
// Kernel E: merge SPLIT_C cross pieces, combine heads (Wo_c), project to
// coords (W_out), accumulate partial Kabsch statistics.
// grid = 64 blocks (4 per batch), 256 threads, 1 row/thread.
// ============================================================================
__global__ __launch_bounds__(256) void coords_stats(
    const float* __restrict__ Wo_c,  const float* __restrict__ bo_c,
    const float* __restrict__ W_out, const float* __restrict__ b_out)
{
    __shared__ float sWo[EDIM*EDIM], sbo[EDIM], sWt[3*EDIM], sbt[3];
    __shared__ float sred2[8][15];
    const int tid  = threadIdx.x;
    const int b    = blockIdx.x >> 2;
    const int part = blockIdx.x & 3;
    for (int i = tid; i < EDIM*EDIM; i += 256) sWo[i] = Wo_c[i];
    if (tid < EDIM)   sbo[tid] = bo_c[tid];
    if (tid < 3*EDIM) sWt[tid] = W_out[tid];
    if (tid < 3)      sbt[tid] = b_out[tid];
    __syncthreads();

    const int n = part*256 + tid;
    float ohv[EDIM];
    #pragma unroll
    for (int h = 0; h < HEADS; h++) {
        const size_t idx = (size_t)(b*HEADS + h)*NPTS + n;
        float a0 = 0.f, a1 = 0.f, a2 = 0.f, lw = 0.f;
        #pragma unroll
        for (int p = 0; p < SPLIT_C; p++) {
            const float4 A = g_po_c[(size_t)p*BATCH*HEADS*NPTS + idx];
            a0 += A.x; a1 += A.y; a2 += A.z; lw += A.w;
        }
        const float invl = 1.0f / lw;
        ohv[h*3+0] = a0 * invl;
        ohv[h*3+1] = a1 * invl;
        ohv[h*3+2] = a2 * invl;
    }

    float z[EDIM];
    #pragma unroll
    for (int e = 0; e < EDIM; e++) {
        float a = sbo[e];
        #pragma unroll
        for (int k = 0; k < EDIM; k++) a = fmaf(sWo[e*EDIM + k], ohv[k], a);
        z[e] = a;
    }
    float co[3];
    #pragma unroll
    for (int i = 0; i < 3; i++) {
        float a = sbt[i];
        #pragma unroll
        for (int e = 0; e < EDIM; e++) a = fmaf(sWt[i*EDIM + e], z[e], a);
        co[i] = a;
    }
    const float* xp = g_x3 + ((size_t)b*NPTS + n)*3;
    const float x0 = xp[0], x1 = xp[1], x2 = xp[2];
    const float B0 = co[0] + x0, B1 = co[1] + x1, B2 = co[2] + x2;

    float vals[15];
    vals[0]=B0*x0; vals[1]=B0*x1; vals[2]=B0*x2;
    vals[3]=B1*x0; vals[4]=B1*x1; vals[5]=B1*x2;
    vals[6]=B2*x0; vals[7]=B2*x1; vals[8]=B2*x2;
    vals[9]=B0; vals[10]=B1; vals[11]=B2;
    vals[12]=x0; vals[13]=x1; vals[14]=x2;
    #pragma unroll
    for (int k = 0; k < 15; k++) {
        #pragma unroll
        for (int off = 16; off; off >>= 1)
            vals[k] += __shfl_xor_sync(0xffffffffu, vals[k], off);
    }
    const int lane = tid & 31, w = tid >> 5;
    if (lane == 0) {
        #pragma unroll
        for (int k = 0; k < 15; k++) sred2[w][k] = vals[k];
    }
    __syncthreads();
    if (tid < 15) {
        float a = 0.f;
        #pragma unroll
        for (int wi = 0; wi < 8; wi++) a += sred2[wi][tid];
        g_statp[(b*4 + part)*16 + tid] = a;
    }
}

// ============================================================================
// Kernel G: fold stats, Kabsch (Newton polar, redundant per thread), and
// out = x3 @ R + t + y_t3.   grid = 64 x 256
// Reference: A = coords+x3 (centroid cP), Bp = x3 (centroid cX).
//   H[i][j] = S[j*3+i] - N*cX[i]*cP[j];  R = polar(H);  t = cP - cX @ R
// ============================================================================
__global__ __launch_bounds__(256) void output_kernel(float* __restrict__ out)
{
    const int row = blockIdx.x*256 + threadIdx.x;   // < 16384
    const int b = row >> 10;

    float st[15];
    #pragma unroll
    for (int k = 0; k < 15; k++) {
        float a = 0.f;
        #pragma unroll
        for (int p = 0; p < 4; p++) a += g_statp[(b*4 + p)*16 + k];
        st[k] = a;
    }
    float cP[3] = { st[9]*(1.0f/NPTS),  st[10]*(1.0f/NPTS), st[11]*(1.0f/NPTS) };
    float cX[3] = { st[12]*(1.0f/NPTS), st[13]*(1.0f/NPTS), st[14]*(1.0f/NPTS) };
    float X[9];
    #pragma unroll
    for (int i = 0; i < 3; i++)
        #pragma unroll
        for (int j = 0; j < 3; j++)
            X[i*3+j] = st[j*3+i] - (float)NPTS * cX[i] * cP[j];

    float nf = 0.f;
    #pragma unroll
    for (int k = 0; k < 9; k++) nf += X[k]*X[k];
    const float inv = rsqrtf(nf);
    #pragma unroll
    for (int k = 0; k < 9; k++) X[k] *= inv;

    #pragma unroll
    for (int it = 0; it < 12; it++) {
        float C[9];
        C[0] = X[4]*X[8] - X[5]*X[7];
        C[1] = X[5]*X[6] - X[3]*X[8];
        C[2] = X[3]*X[7] - X[4]*X[6];
        C[3] = X[2]*X[7] - X[1]*X[8];
        C[4] = X[0]*X[8] - X[2]*X[6];
        C[5] = X[1]*X[6] - X[0]*X[7];
        C[6] = X[1]*X[5] - X[2]*X[4];
        C[7] = X[2]*X[3] - X[0]*X[5];
        C[8] = X[0]*X[4] - X[1]*X[3];
        const float det = X[0]*C[0] + X[1]*C[1] + X[2]*C[2];
        const float hid = 0.5f / det;
        #pragma unroll
        for (int k = 0; k < 9; k++) X[k] = 0.5f*X[k] + C[k]*hid;
    }

    float tv[3];
    #pragma unroll
    for (int j = 0; j < 3; j++)
        tv[j] = cP[j] - (cX[0]*X[0*3+j] + cX[1]*X[1*3+j] + cX[2]*X[2*3+j]);

    const float* yt = g_yt3 + b*3;
    const float* xp = g_x3 + (size_t)row*3;
    const float x0 = xp[0], x1 = xp[1], x2 = xp[2];
    #pragma unroll
    for (int j = 0; j < 3; j++) {
        out[(size_t)row*3 + j] =
            fmaf(x0, X[j], fmaf(x1, X[3+j], fmaf(x2, X[6+j], tv[j] + yt[j])));
    }
}

// ============================================================================
extern "C" void kernel_launch(void* const* d_in, const int* in_sizes, int n_in,
                              void* d_out, int out_size)
{
    (void)in_sizes; (void)n_in; (void)out_size;
    const float* x_orig = (const float*)d_in[0];
    const float* y_orig = (const float*)d_in[1];
    const float* W_in   = (const float*)d_in[2];
    const float* b_in   = (const float*)d_in[3];
    const float* Wqkv_s = (const float*)d_in[4];
    const float* bqkv_s = (const float*)d_in[5];
    const float* Wo_s   = (const float*)d_in[6];
    const float* bo_s   = (const float*)d_in[7];
    const float* Wqkv_c = (const float*)d_in[8];
    const float* bqkv_c = (const float*)d_in[9];
    const float* Wo_c   = (const float*)d_in[10];
    const float* bo_c   = (const float*)d_in[11];
    const float* W_out  = (const float*)d_in[12];
    const float* b_out  = (const float*)d_in[13];
    float* out = (float*)d_out;

    prep_qkv_self<<<BB*4, 256>>>(x_orig, y_orig, W_in, b_in, Wqkv_s, bqkv_s);
    attn_kernel<0><<<BB*HEADS*SPLIT_S, 128>>>();              // 1024 blocks
    combine_qkv_cross<<<(BB*NPTS)/256, 256>>>(Wo_s, bo_s, Wqkv_c, bqkv_c);
    attn_kernel<1><<<BATCH*HEADS*SPLIT_C, 128>>>();           // 1024 blocks
    coords_stats<<<BATCH*4, 256>>>(Wo_c, bo_c, W_out, b_out);
    output_kernel<<<(BATCH*NPTS)/256, 256>>>(out);
}

// round 13
// speedup vs baseline: 4.6502x; 2.6340x over previous
#include <cuda_runtime.h>
#include <cstdint>

#define BATCH 16
#define NPTS  1024
#define FDIM  16
#define EDIM  12
#define HEADS 4
#define BB    32            // 2*BATCH (x-slab then y-slab)

// 1/sqrt(3): softmax scale folded into stored q (natural-exp Taylor, no log2e)
#define RSQRT3 0.5773502691896258f

// ---------------- scratch (device globals; no allocation allowed) ----------
__device__ float g_x3  [BATCH*NPTS*3];
__device__ float g_yt3 [BATCH*3];
__device__ float g_q_s [BB*HEADS*NPTS*4];       // pre-scaled q (stride 4)
__device__ float g_kv_s[BB*HEADS*NPTS*8];       // k0,k1,k2,v0 | v1,v2,-,-
__device__ float g_q_c [BATCH*HEADS*NPTS*4];
__device__ float g_kv_c[BATCH*HEADS*NPTS*8];
__device__ float4 g_mom_s[BB*HEADS*20];         // per-(bh): 20 x (den,num0,num1,num2)
__device__ float4 g_mom_c[BATCH*HEADS*20];
__device__ float g_statp[BATCH*4*16];           // 4 partial stat sets per batch

// ============================================================================
// Taylor-moment attention core.
// exp(s) ~= 1 + s + s^2/2 + s^3/6,  s = q.k (q prescaled by 1/sqrt(3)).
// Monomial basis (20), shared by weights (key side) and queries:
//  0:1  1:q0 2:q1 3:q2
//  4:q0^2 5:q0q1 6:q0q2 7:q1^2 8:q1q2 9:q2^2     (weights carry 1/2 on squares)
//  10:q0^3 11:q0^2q1 12:q0^2q2 13:q0q1^2 14:q0q1q2 15:q0q2^2
//  16:q1^3 17:q1^2q2 18:q1q2^2 19:q2^3           (weights carry multinomial/6)
// ============================================================================
__device__ __forceinline__ void attn_poly(const float4* __restrict__ M,
                                          float q0, float q1, float q2, float* o)
{
    float m[20];
    m[0]=1.f;      m[1]=q0;       m[2]=q1;       m[3]=q2;
    m[4]=q0*q0;    m[5]=q0*q1;    m[6]=q0*q2;    m[7]=q1*q1;  m[8]=q1*q2;  m[9]=q2*q2;
    m[10]=m[4]*q0; m[11]=m[4]*q1; m[12]=m[4]*q2; m[13]=m[7]*q0;
    m[14]=m[5]*q2; m[15]=m[9]*q0; m[16]=m[7]*q1; m[17]=m[7]*q2;
    m[18]=m[9]*q1; m[19]=m[9]*q2;
    float dd=0.f, n0=0.f, n1=0.f, n2=0.f;
    #pragma unroll
    for (int i = 0; i < 20; i++) {
        const float4 c = M[i];
        dd = fmaf(m[i], c.x, dd);
        n0 = fmaf(m[i], c.y, n0);
        n1 = fmaf(m[i], c.z, n1);
        n2 = fmaf(m[i], c.w, n2);
    }
    const float inv = 1.0f / dd;
    o[0] = n0*inv; o[1] = n1*inv; o[2] = n2*inv;
}

// ============================================================================
// Kernel A: per (slab,batch,quarter): column means (redundant per quarter),
// center, input proj, self-QKV proj.  grid = 128 blocks, 256 threads.
// ============================================================================
__global__ __launch_bounds__(256) void prep_qkv_self(
    const float* __restrict__ x_orig, const float* __restrict__ y_orig,
    const float* __restrict__ W_in,   const float* __restrict__ b_in,
    const float* __restrict__ Wqkv_s, const float* __restrict__ bqkv_s)
{
    __shared__ float sW[EDIM*FDIM];
    __shared__ float sb[EDIM];
    __shared__ float sWq[36*EDIM];
    __shared__ float sbq[36];
    __shared__ float sred[256];
    __shared__ float smean[FDIM];

    const int tid  = threadIdx.x;
    const int s    = blockIdx.x >> 2;   // 0..31
    const int quar = blockIdx.x & 3;
    const int slab = s >> 4;            // 0 = x, 1 = y
    const int b    = s & 15;
    const float* in = (slab ? y_orig : x_orig) + (size_t)b * NPTS * FDIM;

    for (int i = tid; i < EDIM*FDIM; i += 256) sW[i]  = W_in[i];
    if (tid < EDIM) sb[tid] = b_in[tid];
    for (int i = tid; i < 36*EDIM;   i += 256) sWq[i] = Wqkv_s[i];
    if (tid < 36)   sbq[tid] = bqkv_s[tid];

    // column sums: thread (seg, f) sums 64 rows
    const int f = tid & 15, seg = tid >> 4;
    float acc = 0.f;
    for (int n = seg*64; n < seg*64 + 64; n++) acc += in[(size_t)n*FDIM + f];
    sred[tid] = acc;
    __syncthreads();
    if (tid < FDIM) {
        float m = 0.f;
        #pragma unroll
        for (int g = 0; g < 16; g++) m += sred[g*16 + tid];
        m *= (1.0f / NPTS);
        smean[tid] = m;
        if (slab && quar == 0 && tid < 3) g_yt3[b*3 + tid] = m;
    }
    __syncthreads();

    const int n = quar*256 + tid;
    const float4* rp = (const float4*)(in + (size_t)n*FDIM);
    float xr[FDIM];
    float4 v0 = rp[0], v1 = rp[1], v2 = rp[2], v3 = rp[3];
    xr[0]=v0.x; xr[1]=v0.y; xr[2]=v0.z; xr[3]=v0.w;
    xr[4]=v1.x; xr[5]=v1.y; xr[6]=v1.z; xr[7]=v1.w;
    xr[8]=v2.x; xr[9]=v2.y; xr[10]=v2.z; xr[11]=v2.w;
    xr[12]=v3.x; xr[13]=v3.y; xr[14]=v3.z; xr[15]=v3.w;
    #pragma unroll
    for (int k = 0; k < FDIM; k++) xr[k] -= smean[k];

    if (!slab) {
        float* p = g_x3 + ((size_t)b*NPTS + n)*3;
        p[0] = xr[0]; p[1] = xr[1]; p[2] = xr[2];
    }

    float z[EDIM];
    #pragma unroll
    for (int e = 0; e < EDIM; e++) {
        float a = sb[e];
        #pragma unroll
        for (int k = 0; k < FDIM; k++) a = fmaf(sW[e*FDIM + k], xr[k], a);
        z[e] = a;
    }

    float t[36];
    #pragma unroll
    for (int e2 = 0; e2 < 36; e2++) {
        float a = sbq[e2];
        #pragma unroll
        for (int e = 0; e < EDIM; e++) a = fmaf(sWq[e2*EDIM + e], z[e], a);
        t[e2] = a;
    }

    #pragma unroll
    for (int h = 0; h < HEADS; h++) {
        const size_t rowi = ((size_t)(s*HEADS + h) * NPTS + n);
        float* qp = g_q_s  + rowi*4;
        float* kp = g_kv_s + rowi*8;
        qp[0] = t[h*3+0]*RSQRT3; qp[1] = t[h*3+1]*RSQRT3; qp[2] = t[h*3+2]*RSQRT3;
        kp[0] = t[12+h*3+0]; kp[1] = t[12+h*3+1]; kp[2] = t[12+h*3+2];
        kp[3] = t[24+h*3+0]; kp[4] = t[24+h*3+1]; kp[5] = t[24+h*3+2];
        kp[6] = 0.f; kp[7] = 0.f;
    }
}

// ============================================================================
// Kernel M: key/value moments per (b,h).  grid = NBH blocks x 128 threads.
// Each thread accumulates 20x4 moments over 8 keys; warp shfl + smem reduce.
// ============================================================================
template <int CROSS>
__global__ __launch_bounds__(128) void moments_kernel()
{
    const float* __restrict__ kvg = CROSS ? g_kv_c : g_kv_s;
    float4*      __restrict__ mom = CROSS ? g_mom_c : g_mom_s;
    const int bh  = blockIdx.x;
    const int tid = threadIdx.x;

    float aD[20], a0[20], a1[20], a2[20];
    #pragma unroll
    for (int i = 0; i < 20; i++) { aD[i]=0.f; a0[i]=0.f; a1[i]=0.f; a2[i]=0.f; }

    const float4* src = (const float4*)(kvg + (size_t)bh*NPTS*8);
    for (int r = 0; r < 8; r++) {
        const int n = tid + r*128;
        const float4 A = src[2*n];
        const float4 B = src[2*n+1];
        const float k0=A.x, k1=A.y, k2=A.z, v0=A.w, v1=B.x, v2=B.y;
        float w[20];
        w[0]=1.f; w[1]=k0; w[2]=k1; w[3]=k2;
        w[4]=0.5f*k0*k0; w[5]=k0*k1; w[6]=k0*k2;
        w[7]=0.5f*k1*k1; w[8]=k1*k2; w[9]=0.5f*k2*k2;
        w[10]=(1.f/3.f)*w[4]*k0;  // k0^3/6
        w[11]=w[4]*k1;            // k0^2 k1 / 2
        w[12]=w[4]*k2;
        w[13]=w[7]*k0;
        w[14]=w[5]*k2;            // k0 k1 k2
        w[15]=w[9]*k0;
        w[16]=(1.f/3.f)*w[7]*k1;
        w[17]=w[7]*k2;
        w[18]=w[9]*k1;
        w[19]=(1.f/3.f)*w[9]*k2;
        #pragma unroll
        for (int i = 0; i < 20; i++) {
            aD[i] += w[i];
            a0[i] = fmaf(w[i], v0, a0[i]);
            a1[i] = fmaf(w[i], v1, a1[i]);
            a2[i] = fmaf(w[i], v2, a2[i]);
        }
    }

    #pragma unroll
    for (int i = 0; i < 20; i++) {
        #pragma unroll
        for (int off = 16; off; off >>= 1) {
            aD[i] += __shfl_xor_sync(0xffffffffu, aD[i], off);
            a0[i] += __shfl_xor_sync(0xffffffffu, a0[i], off);
            a1[i] += __shfl_xor_sync(0xffffffffu, a1[i], off);
            a2[i] += __shfl_xor_sync(0xffffffffu, a2[i], off);
        }
    }

    __shared__ float4 sred[4][20];
    const int w_ = tid >> 5, lane = tid & 31;
    if (lane == 0) {
        #pragma unroll
        for (int i = 0; i < 20; i++)
            sred[w_][i] = make_float4(aD[i], a0[i], a1[i], a2[i]);
    }
    __syncthreads();
    if (tid < 20) {
        const float4 a = sred[0][tid], b = sred[1][tid], c = sred[2][tid], d = sred[3][tid];
        mom[bh*20 + tid] = make_float4(a.x+b.x+c.x+d.x, a.y+b.y+c.y+d.y,
                                       a.z+b.z+c.z+d.z, a.w+b.w+c.w+d.w);
    }
}

// ============================================================================
// Kernel C: apply self-attention via moments, combine heads (Wo_s + bo_s),
// then cross-QKV proj. x-slab -> q_c, y-slab -> kv_c.
// grid = 128 blocks (s,quar) x 256 threads.
// ============================================================================
__global__ __launch_bounds__(256) void apply_self_qkv_cross(
    const float* __restrict__ Wo_s,   const float* __restrict__ bo_s,
    const float* __restrict__ Wqkv_c, const float* __restrict__ bqkv_c)
{
    __shared__ float4 sM[HEADS][20];
    __shared__ float sWo[EDIM*EDIM], sbo[EDIM], sWq[36*EDIM], sbq[36];
    const int tid  = threadIdx.x;
    const int s    = blockIdx.x >> 2;
    const int quar = blockIdx.x & 3;

    if (tid < 80) sM[tid/20][tid%20] = g_mom_s[(s*HEADS + tid/20)*20 + tid%20];
    for (int i = tid; i < EDIM*EDIM; i += 256) sWo[i] = Wo_s[i];
    if (tid < EDIM) sbo[tid] = bo_s[tid];
    for (int i = tid; i < 36*EDIM; i += 256) sWq[i] = Wqkv_c[i];
    if (tid < 36) sbq[tid] = bqkv_c[tid];
    __syncthreads();

    const int n    = quar*256 + tid;
    const int slab = s >> 4;
    const int b    = s & 15;

    float ohv[EDIM];
    #pragma unroll
    for (int h = 0; h < HEADS; h++) {
        const float* qp = g_q_s + ((size_t)(s*HEADS + h)*NPTS + n)*4;
        attn_poly(sM[h], qp[0], qp[1], qp[2], ohv + h*3);
    }

    float z[EDIM];
    #pragma unroll
    for (int e = 0; e < EDIM; e++) {
        float a = sbo[e];
        #pragma unroll
        for (int k = 0; k < EDIM; k++) a = fmaf(sWo[e*EDIM + k], ohv[k], a);
        z[e] = a;
    }

    if (slab == 0) {
        #pragma unroll
        for (int h = 0; h < HEADS; h++) {
            float* qp = g_q_c + ((size_t)(b*HEADS + h)*NPTS + n)*4;
            #pragma unroll
            for (int d = 0; d < 3; d++) {
                const int e2 = h*3 + d;
                float a = sbq[e2];
                #pragma unroll
                for (int e = 0; e < EDIM; e++) a = fmaf(sWq[e2*EDIM + e], z[e], a);
                qp[d] = a * RSQRT3;
            }
        }
    } else {
        #pragma unroll
        for (int h = 0; h < HEADS; h++) {
            float* kp = g_kv_c + ((size_t)(b*HEADS + h)*NPTS + n)*8;
            #pragma unroll
            for (int d = 0; d < 3; d++) {
                const int e2k = 12 + h*3 + d;
                const int e2v = 24 + h*3 + d;
                float ak = sbq[e2k], av = sbq[e2v];
                #pragma unroll
                for (int e = 0; e < EDIM; e++) {
                    ak = fmaf(sWq[e2k*EDIM + e], z[e], ak);
                    av = fmaf(sWq[e2v*EDIM + e], z[e], av);
                }
                kp[d]   = ak;
                kp[3+d] = av;
            }
        }
    }
}

// ============================================================================
// Kernel E: apply cross-attention via moments, combine heads (Wo_c), project
// to coords (W_out), accumulate partial Kabsch statistics.
// grid = 64 blocks (b,part) x 256 threads.
// ============================================================================
__global__ __launch_bounds__(256) void apply_cross_stats(
    const float* __restrict__ Wo_c,  const float* __restrict__ bo_c,
    const float* __restrict__ W_out, const float* __restrict__ b_out)
{
    __shared__ float4 sM[HEADS][20];
    __shared__ float sWo[EDIM*EDIM], sbo[EDIM], sWt[3*EDIM], sbt[3];
    __shared__ float sred2[8][15];
    const int tid  = threadIdx.x;
    const int b    = blockIdx.x >> 2;
    const int part = blockIdx.x & 3;

    if (tid < 80) sM[tid/20][tid%20] = g_mom_c[(b*HEADS + tid/20)*20 + tid%20];
    for (int i = tid; i < EDIM*EDIM; i += 256) sWo[i] = Wo_c[i];
    if (tid < EDIM)   sbo[tid] = bo_c[tid];
    if (tid < 3*EDIM) sWt[tid] = W_out[tid];
    if (tid < 3)      sbt[tid] = b_out[tid];
    __syncthreads();

    const int n = part*256 + tid;
    float ohv[EDIM];
    #pragma unroll
    for (int h = 0; h < HEADS; h++) {
        const float* qp = g_q_c + ((size_t)(b*HEADS + h)*NPTS + n)*4;
        attn_poly(sM[h], qp[0], qp[1], qp[2], ohv + h*3);
    }

    float z[EDIM];
    #pragma unroll
    for (int e = 0; e < EDIM; e++) {
        float a = sbo[e];
        #pragma unroll
        for (int k = 0; k < EDIM; k++) a = fmaf(sWo[e*EDIM + k], ohv[k], a);
        z[e] = a;
    }
    float co[3];
    #pragma unroll
    for (int i = 0; i < 3; i++) {
        float a = sbt[i];
        #pragma unroll
        for (int e = 0; e < EDIM; e++) a = fmaf(sWt[i*EDIM + e], z[e], a);
        co[i] = a;
    }
    const float* xp = g_x3 + ((size_t)b*NPTS + n)*3;
    const float x0 = xp[0], x1 = xp[1], x2 = xp[2];
    const float B0 = co[0] + x0, B1 = co[1] + x1, B2 = co[2] + x2;

    float vals[15];
    vals[0]=B0*x0; vals[1]=B0*x1; vals[2]=B0*x2;
    vals[3]=B1*x0; vals[4]=B1*x1; vals[5]=B1*x2;
    vals[6]=B2*x0; vals[7]=B2*x1; vals[8]=B2*x2;
    vals[9]=B0; vals[10]=B1; vals[11]=B2;
    vals[12]=x0; vals[13]=x1; vals[14]=x2;
    #pragma unroll
    for (int k = 0; k < 15; k++) {
        #pragma unroll
        for (int off = 16; off; off >>= 1)
            vals[k] += __shfl_xor_sync(0xffffffffu, vals[k], off);
    }
    const int lane = tid & 31, w = tid >> 5;
    if (lane == 0) {
        #pragma unroll
        for (int k = 0; k < 15; k++) sred2[w][k] = vals[k];
    }
    __syncthreads();
    if (tid < 15) {
        float a = 0.f;
        #pragma unroll
        for (int wi = 0; wi < 8; wi++) a += sred2[wi][tid];
        g_statp[(b*4 + part)*16 + tid] = a;
    }
}

// ============================================================================
// Kernel G: fold stats, Kabsch (Newton polar, redundant per thread), and
// out = x3 @ R + t + y_t3.   grid = 64 x 256
// Reference: A = coords+x3 (centroid cP), Bp = x3 (centroid cX).
//   H[i][j] = S[j*3+i] - N*cX[i]*cP[j];  R = polar(H);  t = cP - cX @ R
// ============================================================================
__global__ __launch_bounds__(256) void output_kernel(float* __restrict__ out)
{
    const int row = blockIdx.x*256 + threadIdx.x;   // < 16384
    const int b = row >> 10;

    float st[15];
    #pragma unroll
    for (int k = 0; k < 15; k++) {
        float a = 0.f;
        #pragma unroll
        for (int p = 0; p < 4; p++) a += g_statp[(b*4 + p)*16 + k];
        st[k] = a;
    }
    float cP[3] = { st[9]*(1.0f/NPTS),  st[10]*(1.0f/NPTS), st[11]*(1.0f/NPTS) };
    float cX[3] = { st[12]*(1.0f/NPTS), st[13]*(1.0f/NPTS), st[14]*(1.0f/NPTS) };
    float X[9];
    #pragma unroll
    for (int i = 0; i < 3; i++)
        #pragma unroll
        for (int j = 0; j < 3; j++)
            X[i*3+j] = st[j*3+i] - (float)NPTS * cX[i] * cP[j];

    float nf = 0.f;
    #pragma unroll
    for (int k = 0; k < 9; k++) nf += X[k]*X[k];
    const float inv = rsqrtf(nf);
    #pragma unroll
    for (int k = 0; k < 9; k++) X[k] *= inv;

    #pragma unroll
    for (int it = 0; it < 12; it++) {
        float C[9];
        C[0] = X[4]*X[8] - X[5]*X[7];
        C[1] = X[5]*X[6] - X[3]*X[8];
        C[2] = X[3]*X[7] - X[4]*X[6];
        C[3] = X[2]*X[7] - X[1]*X[8];
        C[4] = X[0]*X[8] - X[2]*X[6];
        C[5] = X[1]*X[6] - X[0]*X[7];
        C[6] = X[1]*X[5] - X[2]*X[4];
        C[7] = X[2]*X[3] - X[0]*X[5];
        C[8] = X[0]*X[4] - X[1]*X[3];
        const float det = X[0]*C[0] + X[1]*C[1] + X[2]*C[2];
        const float hid = 0.5f / det;
        #pragma unroll
        for (int k = 0; k < 9; k++) X[k] = 0.5f*X[k] + C[k]*hid;
    }

    float tv[3];
    #pragma unroll
    for (int j = 0; j < 3; j++)
        tv[j] = cP[j] - (cX[0]*X[0*3+j] + cX[1]*X[1*3+j] + cX[2]*X[2*3+j]);

    const float* yt = g_yt3 + b*3;
    const float* xp = g_x3 + (size_t)row*3;
    const float x0 = xp[0], x1 = xp[1], x2 = xp[2];
    #pragma unroll
    for (int j = 0; j < 3; j++) {
        out[(size_t)row*3 + j] =
            fmaf(x0, X[j], fmaf(x1, X[3+j], fmaf(x2, X[6+j], tv[j] + yt[j])));
    }
}

// ============================================================================
extern "C" void kernel_launch(void* const* d_in, const int* in_sizes, int n_in,
                              void* d_out, int out_size)
{
    (void)in_sizes; (void)n_in; (void)out_size;
    const float* x_orig = (const float*)d_in[0];
    const float* y_orig = (const float*)d_in[1];
    const float* W_in   = (const float*)d_in[2];
    const float* b_in   = (const float*)d_in[3];
    const float* Wqkv_s = (const float*)d_in[4];
    const float* bqkv_s = (const float*)d_in[5];
    const float* Wo_s   = (const float*)d_in[6];
    const float* bo_s   = (const float*)d_in[7];
    const float* Wqkv_c = (const float*)d_in[8];
    const float* bqkv_c = (const float*)d_in[9];
    const float* Wo_c   = (const float*)d_in[10];
    const float* bo_c   = (const float*)d_in[11];
    const float* W_out  = (const float*)d_in[12];
    const float* b_out  = (const float*)d_in[13];
    float* out = (float*)d_out;

    prep_qkv_self<<<BB*4, 256>>>(x_orig, y_orig, W_in, b_in, Wqkv_s, bqkv_s);
    moments_kernel<0><<<BB*HEADS, 128>>>();                   // 128 blocks
    apply_self_qkv_cross<<<BB*4, 256>>>(Wo_s, bo_s, Wqkv_c, bqkv_c);
    moments_kernel<1><<<BATCH*HEADS, 128>>>();                // 64 blocks
    apply_cross_stats<<<BATCH*4, 256>>>(Wo_c, bo_c, W_out, b_out);
    output_kernel<<<(BATCH*NPTS)/256, 256>>>(out);
}